// round 12
// baseline (speedup 1.0000x reference)
#include <cuda_runtime.h>
#include <cuda_bf16.h>
#include <math.h>
#include <stdint.h>

#define DEV_INLINE __device__ __forceinline__

constexpr int Bn = 32, Ln = 256, DNn = 512;
constexpr int ROWS = Bn * Ln;            // 8192 (b,l) rows
constexpr int EROWS = ROWS * Ln;         // 2,097,152 edge rows
constexpr int FNn = 1024;
constexpr float EPSc = 1e-5f;

// ---------------- device scratch ----------------
__device__ float g_hln[ROWS * DNn];
__device__ float g_qkv[ROWS * 3 * DNn];
__device__ float g_vatt[ROWS * DNn];
__device__ float g_h2[ROWS * DNn];
__device__ float g_hff[ROWS * DNn];
__device__ float g_t[ROWS * FNn];
__device__ uint32_t g_Hb[(size_t)EROWS * 16];     // H_hat + mask, bf16x2
__device__ uint32_t g_gateb[(size_t)EROWS * 16];  // sigmoid(G+mask), bf16x2
__device__ __nv_bfloat16 g_Ab[(size_t)EROWS * 32];// A_hat (scaled), bf16
// bf16 fragment-packed edge weights (see packB); bf16 K and V copies
__device__ __nv_bfloat16 g_WEGb[64 * 64];
__device__ __nv_bfloat16 g_WOeb[32 * 64];
__device__ __nv_bfloat16 g_We1b[64 * 128];
__device__ __nv_bfloat16 g_We2b[128 * 64];
__device__ __nv_bfloat162 g_kb[(size_t)ROWS * 256];   // [(row)*256 + dp*32 + h]
__device__ __nv_bfloat162 g_vb[(size_t)ROWS * 256];   // [(row)*256 + kp*32 + h]

DEV_INLINE uint32_t packbf(float a, float b) {
    __nv_bfloat162 h2 = __floats2bfloat162_rn(a, b);
    return *(uint32_t*)&h2;
}

DEV_INLINE float to_tf32(float x) {
    float y;
    asm("cvt.rna.tf32.f32 %0, %1;" : "=f"(y) : "f"(x));
    return y;
}

DEV_INLINE void mma8(float c[4], uint32_t a0, uint32_t a1, uint32_t a2, uint32_t a3,
                     uint32_t b0, uint32_t b1)
{
    asm volatile(
        "mma.sync.aligned.m16n8k8.row.col.f32.tf32.tf32.f32 "
        "{%0,%1,%2,%3},{%4,%5,%6,%7},{%8,%9},{%0,%1,%2,%3};"
        : "+f"(c[0]), "+f"(c[1]), "+f"(c[2]), "+f"(c[3])
        : "r"(a0), "r"(a1), "r"(a2), "r"(a3), "r"(b0), "r"(b1));
}

DEV_INLINE void mma16(float c[4], uint32_t a0, uint32_t a1, uint32_t a2, uint32_t a3,
                      uint32_t b0, uint32_t b1)
{
    asm volatile(
        "mma.sync.aligned.m16n8k16.row.col.f32.bf16.bf16.f32 "
        "{%0,%1,%2,%3},{%4,%5,%6,%7},{%8,%9},{%0,%1,%2,%3};"
        : "+f"(c[0]), "+f"(c[1]), "+f"(c[2]), "+f"(c[3])
        : "r"(a0), "r"(a1), "r"(a2), "r"(a3), "r"(b0), "r"(b1));
}

// smem-B tf32 warp GEMM (h-path)
template<int NTW, int KS>
DEV_INLINE void wgemm(float c[NTW][4], const float* __restrict__ Arow, int lda,
                      const float* __restrict__ Bcol, int ldb, int g, int qt)
{
    #pragma unroll
    for (int ks = 0; ks < KS; ks++) {
        int k = ks * 8;
        uint32_t a0 = __float_as_uint(Arow[(g)     * lda + k + qt]);
        uint32_t a1 = __float_as_uint(Arow[(g + 8) * lda + k + qt]);
        uint32_t a2 = __float_as_uint(Arow[(g)     * lda + k + qt + 4]);
        uint32_t a3 = __float_as_uint(Arow[(g + 8) * lda + k + qt + 4]);
        #pragma unroll
        for (int j = 0; j < NTW; j++) {
            uint32_t b0 = __float_as_uint(Bcol[(k + qt)     * ldb + j * 8 + g]);
            uint32_t b1 = __float_as_uint(Bcol[(k + qt + 4) * ldb + j * 8 + g]);
            mma8(c[j], a0, a1, a2, a3, b0, b1);
        }
    }
}

// bf16 warp GEMM, m16n8k16. A in smem as u32 (bf16x2), sb2 = u32 words per row.
template<int TM, int NTW, int S, int N>
DEV_INLINE void wgemm_b(float c[TM][NTW][4], const uint32_t* __restrict__ As, int sb2,
                        const uint32_t* __restrict__ Bp, int g, int qt)
{
    #pragma unroll
    for (int t = 0; t < (S + 1) / 2; t++) {
        uint4 bq[NTW];
        #pragma unroll
        for (int j = 0; j < NTW; j++)
            bq[j] = *(const uint4*)&Bp[(t * (N * 4) + (j * 8 + g) * 4 + qt) * 4];
        #pragma unroll
        for (int se = 0; se < 2; se++) {
            int s = 2 * t + se;
            if (s >= S) break;
            #pragma unroll
            for (int tm = 0; tm < TM; tm++) {
                const uint32_t* Ar = As + tm * 16 * sb2;
                uint32_t a0 = Ar[(g)     * sb2 + 8 * s + qt];
                uint32_t a2 = Ar[(g)     * sb2 + 8 * s + qt + 4];
                uint32_t a1 = Ar[(g + 8) * sb2 + 8 * s + qt];
                uint32_t a3 = Ar[(g + 8) * sb2 + 8 * s + qt + 4];
                #pragma unroll
                for (int j = 0; j < NTW; j++) {
                    uint32_t b0 = se ? bq[j].z : bq[j].x;
                    uint32_t b1 = se ? bq[j].w : bq[j].y;
                    mma16(c[tm][j], a0, a1, a2, a3, b0, b1);
                }
            }
        }
    }
}

// bf16 fragment pack index: element (k,n) of a KxN col-fragment weight.
DEV_INLINE int packB(int n, int k, int N) {
    int p = k >> 1, lo = k & 1;
    int qt = p & 3, half = (p >> 2) & 1, s = p >> 3;
    int t = s >> 1, se = s & 1;
    int u32i = (t * (N * 4) + n * 4 + qt) * 4 + se * 2 + half;
    return u32i * 2 + lo;
}

__global__ void pack_weights(const float* __restrict__ W_E, const float* __restrict__ W_G,
                             const float* __restrict__ W_Oe, const float* __restrict__ W_e1,
                             const float* __restrict__ W_e2)
{
    int i = blockIdx.x * 256 + threadIdx.x;
    if (i < 4096) {                       // WEG: K=64, N=64
        int k = i >> 6, n = i & 63;
        float v = n < 32 ? W_E[k * 32 + n] : W_G[k * 32 + n - 32];
        g_WEGb[packB(n, k, 64)] = __float2bfloat16(v);
    } else if (i < 6144) {                // WOe: K=32, N=64
        int j = i - 4096; int k = j >> 6, n = j & 63;
        g_WOeb[packB(n, k, 64)] = __float2bfloat16(W_Oe[j]);
    } else if (i < 14336) {               // We1: K=64, N=128
        int j = i - 6144; int k = j >> 7, n = j & 127;
        g_We1b[packB(n, k, 128)] = __float2bfloat16(W_e1[j]);
    } else if (i < 22528) {               // We2: K=128, N=64
        int j = i - 14336; int k = j >> 6, n = j & 63;
        g_We2b[packB(n, k, 64)] = __float2bfloat16(W_e2[j]);
    }
}

// K and V -> interleaved bf16 pairs (both use layout [row*256 + p*32 + h])
__global__ void kvconv_kernel()
{
    int idx = blockIdx.x * 256 + threadIdx.x;    // over ROWS*512
    int row = idx >> 9, t = idx & 511;
    int half = t >> 8, u = t & 255;
    int dp = u >> 5, h = u & 31;
    const float* base = g_qkv + (size_t)row * 1536 + 512 + half * 512 + dp * 64 + h;
    __nv_bfloat162 v = __floats2bfloat162_rn(base[0], base[32]);
    if (half == 0) g_kb[(size_t)row * 256 + u] = v;
    else           g_vb[(size_t)row * 256 + u] = v;
}

// ---------------- QK precompute: A_hat for all (b,l,m,h) -------------------
constexpr int QK_SMEM_BYTES = 64 * 256 * 4;   // 65536

__global__ void __launch_bounds__(256, 3) qk_kernel()
{
    extern __shared__ uint32_t ks[];   // [64][256] bf16x2 words
    int blk = blockIdx.x;
    int lt = blk & 15, mt = (blk >> 4) & 3, b = blk >> 6;
    int m0 = mt * 64;
    int tid = threadIdx.x;

    const uint4* Ksrc = (const uint4*)(g_kb + ((size_t)(b * 256) + m0) * 256);
    uint4* Kdst = (uint4*)ks;
    #pragma unroll
    for (int i = 0; i < 16; i++)
        Kdst[tid + i * 256] = Ksrc[tid + i * 256];
    __syncthreads();

    int h = tid & 31, grp = tid >> 5;
    #pragma unroll
    for (int li = 0; li < 2; li++) {
        int l  = lt * 16 + grp + li * 8;
        int bl = b * 256 + l;
        float q[16];
        const float* Qp = g_qkv + (size_t)bl * 1536 + h;
        #pragma unroll
        for (int d = 0; d < 16; d++) q[d] = Qp[d * 32];
        __nv_bfloat16* Adst = g_Ab + ((size_t)bl * 256 + m0) * 32 + h;
        for (int m = 0; m < 64; m++) {
            const uint32_t* Kp = ks + m * 256 + h;
            float a = 0.f;
            #pragma unroll
            for (int dp = 0; dp < 8; dp++) {
                float2 kv = __bfloat1622float2(*(const __nv_bfloat162*)&Kp[dp * 32]);
                a += q[2 * dp] * kv.x + q[2 * dp + 1] * kv.y;
            }
            Adst[(size_t)m * 32] = __float2bfloat16(a * 0.25f);
        }
    }
}

// ---------------- LayerNorm over 512, one block per row ----------------
__global__ void __launch_bounds__(128) ln512_kernel(
    const float* __restrict__ x, const float* __restrict__ g,
    const float* __restrict__ b, float* __restrict__ y)
{
    int row = blockIdx.x, tid = threadIdx.x;
    const float4* xr = (const float4*)(x + (size_t)row * 512);
    float4 v = xr[tid];
    float s  = v.x + v.y + v.z + v.w;
    float s2 = v.x*v.x + v.y*v.y + v.z*v.z + v.w*v.w;
    #pragma unroll
    for (int o = 16; o; o >>= 1) {
        s  += __shfl_xor_sync(0xffffffffu, s,  o);
        s2 += __shfl_xor_sync(0xffffffffu, s2, o);
    }
    __shared__ float aS[4], aS2[4];
    if ((tid & 31) == 0) { aS[tid >> 5] = s; aS2[tid >> 5] = s2; }
    __syncthreads();
    s  = aS[0] + aS[1] + aS[2] + aS[3];
    s2 = aS2[0] + aS2[1] + aS2[2] + aS2[3];
    float mean = s * (1.f / 512.f);
    float rstd = rsqrtf(s2 * (1.f / 512.f) - mean * mean + EPSc);
    int c = tid * 4;
    float4 gv = *(const float4*)(g + c);
    float4 bv = *(const float4*)(b + c);
    float4 o;
    o.x = (v.x - mean) * rstd * gv.x + bv.x;
    o.y = (v.y - mean) * rstd * gv.y + bv.y;
    o.z = (v.z - mean) * rstd * gv.z + bv.z;
    o.w = (v.w - mean) * rstd * gv.w + bv.w;
    ((float4*)(y + (size_t)row * 512))[tid] = o;
}

// ---------------- tf32 tensor GEMM for h-path (precision-proven) --------------
constexpr int TG_SMEM_BYTES = (128 * 68 + 64 * 72) * 4;   // 53248
template<int MODE>
__global__ void __launch_bounds__(256) tgemm_tf(
    const float* __restrict__ A, const float* __restrict__ B, float* __restrict__ C,
    const float* __restrict__ bias, const float* __restrict__ res,
    int M, int N, int K)
{
    extern __shared__ float ts[];
    float* As = ts;              // 128 x 68
    float* Bs = ts + 128 * 68;   // 64 x 72
    int tid = threadIdx.x;
    int row0 = blockIdx.y * 128, col0 = blockIdx.x * 64;
    int w = tid >> 5;
    int g = (tid & 31) >> 2, qt = tid & 3;
    float acc[8][4] = {};

    for (int k0 = 0; k0 < K; k0 += 64) {
        #pragma unroll
        for (int i = 0; i < 8; i++) {
            int idx = tid + i * 256;
            int r = idx >> 4, c4 = idx & 15;
            float4 v = *(const float4*)&A[(size_t)(row0 + r) * K + k0 + c4 * 4];
            float4 t;
            t.x = to_tf32(v.x); t.y = to_tf32(v.y); t.z = to_tf32(v.z); t.w = to_tf32(v.w);
            *(float4*)&As[r * 68 + c4 * 4] = t;
        }
        #pragma unroll
        for (int i = 0; i < 4; i++) {
            int idx = tid + i * 256;
            int r = idx >> 4, c4 = idx & 15;
            float4 v = *(const float4*)&B[(size_t)(k0 + r) * N + col0 + c4 * 4];
            float4 t;
            t.x = to_tf32(v.x); t.y = to_tf32(v.y); t.z = to_tf32(v.z); t.w = to_tf32(v.w);
            *(float4*)&Bs[r * 72 + c4 * 4] = t;
        }
        __syncthreads();
        wgemm<8, 8>(acc, As + w * 16 * 68, 68, Bs, 72, g, qt);
        __syncthreads();
    }
    #pragma unroll
    for (int j = 0; j < 8; j++) {
        int col = col0 + j * 8 + 2 * qt;
        #pragma unroll
        for (int hf = 0; hf < 2; hf++) {
            int r = row0 + w * 16 + g + hf * 8;
            float v0 = acc[j][hf * 2 + 0] + bias[col];
            float v1 = acc[j][hf * 2 + 1] + bias[col + 1];
            if (MODE == 1) {
                float2 rv = *(const float2*)&res[(size_t)r * N + col];
                v0 += rv.x; v1 += rv.y;
            }
            if (MODE == 2) {
                v0 = v0 > 0.f ? v0 : __expf(v0) - 1.f;
                v1 = v1 > 0.f ? v1 : __expf(v1) - 1.f;
            }
            float2 ov; ov.x = v0; ov.y = v1;
            *(float2*)&C[(size_t)r * N + col] = ov;
        }
    }
}

// LN of 64 rows x 64 cols: fp32 src (stride sstr) -> bf16x2 dst (dsb2 u32/row).
DEV_INLINE void ln64b(const float* __restrict__ src, int sstr, uint32_t* __restrict__ dst,
                      int dsb2, const float* __restrict__ gam,
                      const float* __restrict__ bet, int tid)
{
    int r = tid >> 2, sub = tid & 3;
    const float* p = src + r * sstr + sub * 16;
    float x[16]; float s = 0.f, s2 = 0.f;
    #pragma unroll
    for (int i = 0; i < 16; i += 4) {
        float4 v = *(const float4*)(p + i);
        x[i] = v.x; x[i+1] = v.y; x[i+2] = v.z; x[i+3] = v.w;
    }
    #pragma unroll
    for (int i = 0; i < 16; i++) { s += x[i]; s2 += x[i] * x[i]; }
    s  += __shfl_xor_sync(0xffffffffu, s, 1);  s  += __shfl_xor_sync(0xffffffffu, s, 2);
    s2 += __shfl_xor_sync(0xffffffffu, s2, 1); s2 += __shfl_xor_sync(0xffffffffu, s2, 2);
    float mean = s * (1.f / 64.f);
    float rstd = rsqrtf(s2 * (1.f / 64.f) - mean * mean + EPSc);
    uint32_t* d = dst + r * dsb2 + sub * 8;
    #pragma unroll
    for (int i = 0; i < 16; i += 2) {
        int c = sub * 16 + i;
        float y0 = (x[i]     - mean) * rstd * gam[c]     + bet[c];
        float y1 = (x[i + 1] - mean) * rstd * gam[c + 1] + bet[c + 1];
        d[i >> 1] = packbf(y0, y1);
    }
}

// Fused: load e tile from global, keep fp32 copy in sX, LN -> bf16x2 sXb.
DEV_INLINE void ln64g(const float* __restrict__ eg, float* __restrict__ sX,
                      uint32_t* __restrict__ sXb,
                      const float* __restrict__ gam, const float* __restrict__ bet, int tid)
{
    int r = tid >> 2, sub = tid & 3;
    const float* p = eg + r * 64 + sub * 16;
    float* q = sX + r * 68 + sub * 16;
    float x[16]; float s = 0.f, s2 = 0.f;
    #pragma unroll
    for (int i = 0; i < 16; i += 4) {
        float4 v = *(const float4*)(p + i);
        *(float4*)(q + i) = v;
        x[i] = v.x; x[i+1] = v.y; x[i+2] = v.z; x[i+3] = v.w;
    }
    #pragma unroll
    for (int i = 0; i < 16; i++) { s += x[i]; s2 += x[i] * x[i]; }
    s  += __shfl_xor_sync(0xffffffffu, s, 1);  s  += __shfl_xor_sync(0xffffffffu, s, 2);
    s2 += __shfl_xor_sync(0xffffffffu, s2, 1); s2 += __shfl_xor_sync(0xffffffffu, s2, 2);
    float mean = s * (1.f / 64.f);
    float rstd = rsqrtf(s2 * (1.f / 64.f) - mean * mean + EPSc);
    uint32_t* d = sXb + r * 36 + sub * 8;
    #pragma unroll
    for (int i = 0; i < 16; i += 2) {
        int c = sub * 16 + i;
        float y0 = (x[i]     - mean) * rstd * gam[c]     + bet[c];
        float y1 = (x[i + 1] - mean) * rstd * gam[c + 1] + bet[c + 1];
        d[i >> 1] = packbf(y0, y1);
    }
}

// ---------------- edge pipeline: 64 rows/CTA, 256 threads, 3 CTA/SM ------------
constexpr int EA_SMEM_BYTES = (4352 + 2304 + 1280 + 4352) * 4;  // 49152

__global__ void __launch_bounds__(256, 3) ea_kernel(
    const float* __restrict__ e, const float* __restrict__ mask,
    const float* __restrict__ lng, const float* __restrict__ lnb,
    const float* __restrict__ flg, const float* __restrict__ flb,
    const float* __restrict__ b_E,  const float* __restrict__ b_G,
    const float* __restrict__ b_Oe, const float* __restrict__ b_e1,
    const float* __restrict__ b_e2,
    float* __restrict__ e_out)
{
    extern __shared__ float sm[];
    float*    sX  = sm;                          // 64 x 68 fp32 (e, then e2)
    uint32_t* sXb = (uint32_t*)(sm + 4352);      // 64 x 36 u32 (eln/eff bf16x2)
    uint32_t* sAb = (uint32_t*)(sm + 6656);      // 64 x 20 u32 (H bf16x2)
    uint32_t* sTb = (uint32_t*)(sm + 7936);      // 64 x 68 u32 (T bf16x2)

    int tid = threadIdx.x;
    int blk = blockIdx.x;
    int bl  = blk >> 2, quad = blk & 3;
    int m0  = quad * 64;
    size_t R0 = (size_t)bl * 256 + m0;

    int w   = tid >> 5;
    int wm2 = w >> 2, wn = w & 3;       // rows wm2*32, col quarter wn
    int g   = (tid & 31) >> 2, qt = tid & 3;
    int rowb = wm2 * 32;

    const uint32_t* WEGu = (const uint32_t*)g_WEGb;
    const uint32_t* WOeu = (const uint32_t*)g_WOeb;
    const uint32_t* We1u = (const uint32_t*)g_We1b;
    const uint32_t* We2u = (const uint32_t*)g_We2b;

    // Pa: load e + LN(e) -> sX (fp32 copy) and sXb (bf16)
    ln64g(e + R0 * 64, sX, sXb, lng, lnb, tid);
    __syncthreads();

    // Pb: GEMM1 (E|G)
    float c1[2][2][4] = {};
    wgemm_b<2, 2, 4, 64>(c1, sXb + rowb * 36, 36, WEGu + wn * 256, g, qt);
    __syncthreads();

    // Pc: epilogue — wn<2: H (A from g_Ab, cols 0..31) -> g_Hb + sAb ;
    //                wn>=2: gate -> g_gateb
    {
        #pragma unroll
        for (int tm = 0; tm < 2; tm++) {
            float mk0 = mask[(size_t)bl * 256 + m0 + rowb + tm * 16 + g];
            float mk1 = mask[(size_t)bl * 256 + m0 + rowb + tm * 16 + g + 8];
            #pragma unroll
            for (int j = 0; j < 2; j++) {
                int colg = wn * 16 + j * 8 + 2 * qt;
                if (wn < 2) {
                    int col = colg;
                    float bv0 = b_E[col], bv1 = b_E[col + 1];
                    #pragma unroll
                    for (int hf = 0; hf < 2; hf++) {
                        int r = rowb + tm * 16 + g + hf * 8;
                        uint32_t aw = ((const uint32_t*)g_Ab)[(R0 + r) * 16 + (col >> 1)];
                        float2 Af = __bfloat1622float2(*(__nv_bfloat162*)&aw);
                        float H0 = fminf(fmaxf(Af.x, -5.f), 5.f) + c1[tm][j][hf * 2 + 0] + bv0;
                        float H1 = fminf(fmaxf(Af.y, -5.f), 5.f) + c1[tm][j][hf * 2 + 1] + bv1;
                        float mk = hf ? mk1 : mk0;
                        g_Hb[(R0 + r) * 16 + (col >> 1)] = packbf(H0 + mk, H1 + mk);
                        sAb[r * 20 + (col >> 1)] = packbf(H0, H1);
                    }
                } else {
                    int col = colg - 32;
                    float bv0 = b_G[col], bv1 = b_G[col + 1];
                    #pragma unroll
                    for (int hf = 0; hf < 2; hf++) {
                        int r = rowb + tm * 16 + g + hf * 8;
                        float mk = hf ? mk1 : mk0;
                        float g0 = 1.f / (1.f + __expf(-(c1[tm][j][hf * 2 + 0] + bv0 + mk)));
                        float g1 = 1.f / (1.f + __expf(-(c1[tm][j][hf * 2 + 1] + bv1 + mk)));
                        g_gateb[(R0 + r) * 16 + (col >> 1)] = packbf(g0, g1);
                    }
                }
            }
        }
    }
    __syncthreads();

    // Pd: GEMM2  e2 = H @ W_Oe + b + e(sX)   (regs + sX overwrite)
    float e2r[2][2][4];
    {
        float c2[2][2][4] = {};
        wgemm_b<2, 2, 2, 64>(c2, sAb + rowb * 20, 20, WOeu + wn * 256, g, qt);
        #pragma unroll
        for (int tm = 0; tm < 2; tm++)
            #pragma unroll
            for (int j = 0; j < 2; j++) {
                int col = wn * 16 + j * 8 + 2 * qt;
                float bo0 = b_Oe[col], bo1 = b_Oe[col + 1];
                #pragma unroll
                for (int hf = 0; hf < 2; hf++) {
                    int r = rowb + tm * 16 + g + hf * 8;
                    float ev0 = sX[r * 68 + col], ev1 = sX[r * 68 + col + 1];
                    float v0 = c2[tm][j][hf * 2 + 0] + bo0 + ev0;
                    float v1 = c2[tm][j][hf * 2 + 1] + bo1 + ev1;
                    e2r[tm][j][hf * 2 + 0] = v0;
                    e2r[tm][j][hf * 2 + 1] = v1;
                    sX[r * 68 + col]     = v0;
                    sX[r * 68 + col + 1] = v1;
                }
            }
    }
    __syncthreads();

    // Pe: LN(e2) -> sXb (bf16 eff)
    ln64b(sX, 68, sXb, 36, flg, flb, tid);
    __syncthreads();

    // Pf: GEMM3  T = elu(eff @ W_e1 + b) -> sTb, two 16-col halves per warp
    #pragma unroll
    for (int half = 0; half < 2; half++) {
        float c3[2][2][4] = {};
        int cb = wn * 32 + half * 16;
        wgemm_b<2, 2, 4, 128>(c3, sXb + rowb * 36, 36, We1u + cb * 16, g, qt);
        #pragma unroll
        for (int tm = 0; tm < 2; tm++)
            #pragma unroll
            for (int j = 0; j < 2; j++) {
                int col = cb + j * 8 + 2 * qt;
                float bb0 = b_e1[col], bb1 = b_e1[col + 1];
                #pragma unroll
                for (int hf = 0; hf < 2; hf++) {
                    int r = rowb + tm * 16 + g + hf * 8;
                    float v0 = c3[tm][j][hf * 2 + 0] + bb0;
                    float v1 = c3[tm][j][hf * 2 + 1] + bb1;
                    v0 = v0 > 0.f ? v0 : __expf(v0) - 1.f;
                    v1 = v1 > 0.f ? v1 : __expf(v1) - 1.f;
                    sTb[r * 68 + (col >> 1)] = packbf(v0, v1);
                }
            }
    }
    __syncthreads();

    // Pg: GEMM4  e_out = T @ W_e2 + b + e2(regs)
    {
        float c4[2][2][4] = {};
        wgemm_b<2, 2, 8, 64>(c4, sTb + rowb * 68, 68, We2u + wn * 256, g, qt);
        #pragma unroll
        for (int tm = 0; tm < 2; tm++)
            #pragma unroll
            for (int j = 0; j < 2; j++) {
                int col = wn * 16 + j * 8 + 2 * qt;
                float bz0 = b_e2[col], bz1 = b_e2[col + 1];
                #pragma unroll
                for (int hf = 0; hf < 2; hf++) {
                    int r = rowb + tm * 16 + g + hf * 8;
                    float2 ov;
                    ov.x = c4[tm][j][hf * 2 + 0] + bz0 + e2r[tm][j][hf * 2 + 0];
                    ov.y = c4[tm][j][hf * 2 + 1] + bz1 + e2r[tm][j][hf * 2 + 1];
                    *(float2*)&e_out[(R0 + r) * 64 + col] = ov;
                }
            }
    }
}

// ---- softmax + gated V: 2 l's per CTA, bf16 smem (occupancy-preserving) ------
// smem: two 256x40-halfword H/weight buffers (stride 20 u32) + reductions.
constexpr int EB_SMEM_BYTES = (2 * 256 * 20 + 1024) * 4;   // 45056

__global__ void __launch_bounds__(256) eb_kernel()
{
    extern __shared__ uint32_t es[];
    uint32_t* sW0 = es;                 // 256 x 20 u32 (H then weights, bf16)
    uint32_t* sW1 = es + 5120;          // 256 x 20 u32
    float* sRed  = (float*)(es + 10240);   // 512
    float* sRed2 = sRed + 512;             // 512

    int tid = threadIdx.x;
    int blk = blockIdx.x;
    int b   = blk >> 7, lp = blk & 127;
    int bl0 = b * 256 + lp;
    int bl1 = bl0 + 128;

    // stage raw H bf16x2 words
    #pragma unroll
    for (int li = 0; li < 2; li++) {
        const uint4* Hg = (const uint4*)(g_Hb + (size_t)(li ? bl1 : bl0) * 4096);
        uint32_t* sW = li ? sW1 : sW0;
        #pragma unroll
        for (int i = 0; i < 4; i++) {
            int idx = tid + i * 256;          // 1024 uint4
            int m = idx >> 2, q = idx & 3;
            uint4 hv = Hg[idx];
            sW[m * 20 + q * 4 + 0] = hv.x;
            sW[m * 20 + q * 4 + 1] = hv.y;
            sW[m * 20 + q * 4 + 2] = hv.z;
            sW[m * 20 + q * 4 + 3] = hv.w;
        }
    }
    __syncthreads();

    int h = tid & 31, grp = tid >> 5;
    const __nv_bfloat16* sH0h = (const __nv_bfloat16*)sW0;
    const __nv_bfloat16* sH1h = (const __nv_bfloat16*)sW1;

    float p0 = -1e30f, p1 = -1e30f;
    for (int mm = 0; mm < 32; mm++) {
        int m = grp * 32 + mm;
        p0 = fmaxf(p0, __bfloat162float(sH0h[m * 40 + h]));
        p1 = fmaxf(p1, __bfloat162float(sH1h[m * 40 + h]));
    }
    sRed[grp * 32 + h]       = p0;
    sRed[256 + grp * 32 + h] = p1;
    __syncthreads();
    float M0 = -1e30f, M1 = -1e30f;
    #pragma unroll
    for (int gg = 0; gg < 8; gg++) {
        M0 = fmaxf(M0, sRed[gg * 32 + h]);
        M1 = fmaxf(M1, sRed[256 + gg * 32 + h]);
    }

    const uint32_t* gR0 = g_gateb + (size_t)bl0 * 4096;
    const uint32_t* gR1 = g_gateb + (size_t)bl1 * 4096;
    __nv_bfloat16* wW0 = (__nv_bfloat16*)sW0;
    __nv_bfloat16* wW1 = (__nv_bfloat16*)sW1;
    float s0 = 0.f, s1 = 0.f;
    for (int mm = 0; mm < 32; mm++) {
        int m = grp * 32 + mm;
        float w0 = __expf(__bfloat162float(sH0h[m * 40 + h]) - M0);
        float w1 = __expf(__bfloat162float(sH1h[m * 40 + h]) - M1);
        s0 += w0; s1 += w1;
        uint32_t gw0 = gR0[m * 16 + (h >> 1)];
        uint32_t gw1 = gR1[m * 16 + (h >> 1)];
        float2 gf0 = __bfloat1622float2(*(__nv_bfloat162*)&gw0);
        float2 gf1 = __bfloat1622float2(*(__nv_bfloat162*)&gw1);
        wW0[m * 40 + h] = __float2bfloat16(w0 * ((h & 1) ? gf0.y : gf0.x));
        wW1[m * 40 + h] = __float2bfloat16(w1 * ((h & 1) ? gf1.y : gf1.x));
    }
    sRed2[grp * 32 + h]       = s0;
    sRed2[256 + grp * 32 + h] = s1;
    __syncthreads();
    float S0 = 0.f, S1 = 0.f;
    #pragma unroll
    for (int gg = 0; gg < 8; gg++) {
        S0 += sRed2[gg * 32 + h];
        S1 += sRed2[256 + gg * 32 + h];
    }
    float inv0 = 1.f / S0, inv1 = 1.f / S1;

    // V accumulation: one V load serves both l's
    float a0 = 0.f, a1 = 0.f, c0 = 0.f, c1v = 0.f;
    const __nv_bfloat162* Vb = g_vb + (size_t)(b * 256) * 256 + grp * 32 + h;
    #pragma unroll 8
    for (int m = 0; m < 256; m++) {
        float2 vv = __bfloat1622float2(Vb[(size_t)m * 256]);
        float w0 = __bfloat162float(wW0[m * 40 + h]);
        float w1 = __bfloat162float(wW1[m * 40 + h]);
        a0  += w0 * vv.x;
        a1  += w0 * vv.y;
        c0  += w1 * vv.x;
        c1v += w1 * vv.y;
    }
    int k0 = grp * 2;
    g_vatt[(size_t)bl0 * 512 + k0 * 32 + h]       = a0 * inv0;
    g_vatt[(size_t)bl0 * 512 + (k0 + 1) * 32 + h] = a1 * inv0;
    g_vatt[(size_t)bl1 * 512 + k0 * 32 + h]       = c0 * inv1;
    g_vatt[(size_t)bl1 * 512 + (k0 + 1) * 32 + h] = c1v * inv1;
}

// ---------------- launch ----------------
extern "C" void kernel_launch(void* const* d_in, const int* in_sizes, int n_in,
                              void* d_out, int out_size)
{
    const float* h         = (const float*)d_in[0];
    const float* e         = (const float*)d_in[1];
    const float* mask      = (const float*)d_in[2];
    const float* ln_h_g    = (const float*)d_in[3];
    const float* ln_h_b    = (const float*)d_in[4];
    const float* ln_e_g    = (const float*)d_in[5];
    const float* ln_e_b    = (const float*)d_in[6];
    const float* ffn_ln_h_g= (const float*)d_in[7];
    const float* ffn_ln_h_b= (const float*)d_in[8];
    const float* ffn_ln_e_g= (const float*)d_in[9];
    const float* ffn_ln_e_b= (const float*)d_in[10];
    const float* W_qkv     = (const float*)d_in[11];
    const float* b_qkv     = (const float*)d_in[12];
    const float* W_E       = (const float*)d_in[13];
    const float* b_E       = (const float*)d_in[14];
    const float* W_G       = (const float*)d_in[15];
    const float* b_G       = (const float*)d_in[16];
    const float* W_Oh      = (const float*)d_in[17];
    const float* b_Oh      = (const float*)d_in[18];
    const float* W_h1      = (const float*)d_in[19];
    const float* b_h1      = (const float*)d_in[20];
    const float* W_h2      = (const float*)d_in[21];
    const float* b_h2      = (const float*)d_in[22];
    const float* W_Oe      = (const float*)d_in[23];
    const float* b_Oe      = (const float*)d_in[24];
    const float* W_e1      = (const float*)d_in[25];
    const float* b_e1      = (const float*)d_in[26];
    const float* W_e2      = (const float*)d_in[27];
    const float* b_e2      = (const float*)d_in[28];

    float* h_out = (float*)d_out;
    float* e_out = (float*)d_out + (size_t)ROWS * DNn;

    float *p_hln, *p_qkv, *p_vatt, *p_h2, *p_hff, *p_t;
    cudaGetSymbolAddress((void**)&p_hln,  g_hln);
    cudaGetSymbolAddress((void**)&p_qkv,  g_qkv);
    cudaGetSymbolAddress((void**)&p_vatt, g_vatt);
    cudaGetSymbolAddress((void**)&p_h2,   g_h2);
    cudaGetSymbolAddress((void**)&p_hff,  g_hff);
    cudaGetSymbolAddress((void**)&p_t,    g_t);

    cudaFuncSetAttribute(ea_kernel, cudaFuncAttributeMaxDynamicSharedMemorySize,
                         EA_SMEM_BYTES);
    cudaFuncSetAttribute(eb_kernel, cudaFuncAttributeMaxDynamicSharedMemorySize,
                         EB_SMEM_BYTES);
    cudaFuncSetAttribute(qk_kernel, cudaFuncAttributeMaxDynamicSharedMemorySize,
                         QK_SMEM_BYTES);
    cudaFuncSetAttribute(tgemm_tf<0>, cudaFuncAttributeMaxDynamicSharedMemorySize,
                         TG_SMEM_BYTES);
    cudaFuncSetAttribute(tgemm_tf<1>, cudaFuncAttributeMaxDynamicSharedMemorySize,
                         TG_SMEM_BYTES);
    cudaFuncSetAttribute(tgemm_tf<2>, cudaFuncAttributeMaxDynamicSharedMemorySize,
                         TG_SMEM_BYTES);

    // 0) pack edge weights (bf16 fragments)
    pack_weights<<<88, 256>>>(W_E, W_G, W_Oe, W_e1, W_e2);
    // 1) h_ln
    ln512_kernel<<<ROWS, 128>>>(h, ln_h_g, ln_h_b, p_hln);
    // 2) QKV = h_ln @ W_qkv + b_qkv   (tf32)
    tgemm_tf<0><<<dim3(1536/64, ROWS/128), 256, TG_SMEM_BYTES>>>(p_hln, W_qkv, p_qkv,
                                                  b_qkv, nullptr, ROWS, 1536, 512);
    // 2.5) K,V -> bf16 interleaved copies
    kvconv_kernel<<<ROWS * 2, 256>>>();
    // 2.6) QK precompute: A_hat (K tile reused across 16 l's)
    qk_kernel<<<Bn * 4 * 16, 256, QK_SMEM_BYTES>>>();
    // 3) edge pipeline (writes e_out, g_Hb(+mask), g_gateb)
    ea_kernel<<<ROWS * 4, 256, EA_SMEM_BYTES>>>(e, mask, ln_e_g, ln_e_b,
        ffn_ln_e_g, ffn_ln_e_b, b_E, b_G, b_Oe, b_e1, b_e2, e_out);
    // 4) softmax + gated V accumulation, 2 l's/CTA, bf16 smem (writes g_vatt)
    eb_kernel<<<ROWS / 2, 256, EB_SMEM_BYTES>>>();
    // 5) h2 = V_att @ W_Oh + b + h
    tgemm_tf<1><<<dim3(512/64, ROWS/128), 256, TG_SMEM_BYTES>>>(p_vatt, W_Oh, p_h2,
                                                 b_Oh, h, ROWS, 512, 512);
    // 6) h_ff = LN(h2)
    ln512_kernel<<<ROWS, 128>>>(p_h2, ffn_ln_h_g, ffn_ln_h_b, p_hff);
    // 7) t = elu(h_ff @ W_h1 + b)
    tgemm_tf<2><<<dim3(1024/64, ROWS/128), 256, TG_SMEM_BYTES>>>(p_hff, W_h1, p_t,
                                                  b_h1, nullptr, ROWS, 1024, 512);
    // 8) h_out = t @ W_h2 + b + h2
    tgemm_tf<1><<<dim3(512/64, ROWS/128), 256, TG_SMEM_BYTES>>>(p_t, W_h2, h_out,
                                                 b_h2, p_h2, ROWS, 512, 1024);
}

// round 13
// speedup vs baseline: 1.0978x; 1.0978x over previous
#include <cuda_runtime.h>
#include <cuda_bf16.h>
#include <math.h>
#include <stdint.h>

#define DEV_INLINE __device__ __forceinline__

constexpr int Bn = 32, Ln = 256, DNn = 512;
constexpr int ROWS = Bn * Ln;            // 8192 (b,l) rows
constexpr int EROWS = ROWS * Ln;         // 2,097,152 edge rows
constexpr int FNn = 1024;
constexpr float EPSc = 1e-5f;

// ---------------- device scratch ----------------
__device__ float g_hln[ROWS * DNn];
__device__ float g_qkv[ROWS * 3 * DNn];       // only Q region (cols 0..511) written
__device__ float g_vatt[ROWS * DNn];
__device__ float g_h2[ROWS * DNn];
__device__ float g_hff[ROWS * DNn];
__device__ float g_t[ROWS * FNn];
__device__ uint32_t g_Hb[(size_t)EROWS * 16];     // H_hat + mask, bf16x2
__device__ uint32_t g_gateb[(size_t)EROWS * 16];  // sigmoid(G+mask), bf16x2
__device__ __nv_bfloat16 g_Ab[(size_t)EROWS * 32];// A_hat (scaled), bf16
// bf16 fragment-packed edge weights (see packB); bf16 K and V
__device__ __nv_bfloat16 g_WEGb[64 * 64];
__device__ __nv_bfloat16 g_WOeb[32 * 64];
__device__ __nv_bfloat16 g_We1b[64 * 128];
__device__ __nv_bfloat16 g_We2b[128 * 64];
__device__ __nv_bfloat162 g_kb[(size_t)ROWS * 256];   // [(row)*256 + dp*32 + h]
__device__ __nv_bfloat162 g_vb[(size_t)ROWS * 256];   // [(row)*256 + kp*32 + h]

DEV_INLINE uint32_t packbf(float a, float b) {
    __nv_bfloat162 h2 = __floats2bfloat162_rn(a, b);
    return *(uint32_t*)&h2;
}

DEV_INLINE float to_tf32(float x) {
    float y;
    asm("cvt.rna.tf32.f32 %0, %1;" : "=f"(y) : "f"(x));
    return y;
}

DEV_INLINE void mma8(float c[4], uint32_t a0, uint32_t a1, uint32_t a2, uint32_t a3,
                     uint32_t b0, uint32_t b1)
{
    asm volatile(
        "mma.sync.aligned.m16n8k8.row.col.f32.tf32.tf32.f32 "
        "{%0,%1,%2,%3},{%4,%5,%6,%7},{%8,%9},{%0,%1,%2,%3};"
        : "+f"(c[0]), "+f"(c[1]), "+f"(c[2]), "+f"(c[3])
        : "r"(a0), "r"(a1), "r"(a2), "r"(a3), "r"(b0), "r"(b1));
}

DEV_INLINE void mma16(float c[4], uint32_t a0, uint32_t a1, uint32_t a2, uint32_t a3,
                      uint32_t b0, uint32_t b1)
{
    asm volatile(
        "mma.sync.aligned.m16n8k16.row.col.f32.bf16.bf16.f32 "
        "{%0,%1,%2,%3},{%4,%5,%6,%7},{%8,%9},{%0,%1,%2,%3};"
        : "+f"(c[0]), "+f"(c[1]), "+f"(c[2]), "+f"(c[3])
        : "r"(a0), "r"(a1), "r"(a2), "r"(a3), "r"(b0), "r"(b1));
}

// smem-B tf32 warp GEMM (h-path)
template<int NTW, int KS>
DEV_INLINE void wgemm(float c[NTW][4], const float* __restrict__ Arow, int lda,
                      const float* __restrict__ Bcol, int ldb, int g, int qt)
{
    #pragma unroll
    for (int ks = 0; ks < KS; ks++) {
        int k = ks * 8;
        uint32_t a0 = __float_as_uint(Arow[(g)     * lda + k + qt]);
        uint32_t a1 = __float_as_uint(Arow[(g + 8) * lda + k + qt]);
        uint32_t a2 = __float_as_uint(Arow[(g)     * lda + k + qt + 4]);
        uint32_t a3 = __float_as_uint(Arow[(g + 8) * lda + k + qt + 4]);
        #pragma unroll
        for (int j = 0; j < NTW; j++) {
            uint32_t b0 = __float_as_uint(Bcol[(k + qt)     * ldb + j * 8 + g]);
            uint32_t b1 = __float_as_uint(Bcol[(k + qt + 4) * ldb + j * 8 + g]);
            mma8(c[j], a0, a1, a2, a3, b0, b1);
        }
    }
}

// bf16 warp GEMM, m16n8k16. A in smem as u32 (bf16x2), sb2 = u32 words per row.
template<int TM, int NTW, int S, int N>
DEV_INLINE void wgemm_b(float c[TM][NTW][4], const uint32_t* __restrict__ As, int sb2,
                        const uint32_t* __restrict__ Bp, int g, int qt)
{
    #pragma unroll
    for (int t = 0; t < (S + 1) / 2; t++) {
        uint4 bq[NTW];
        #pragma unroll
        for (int j = 0; j < NTW; j++)
            bq[j] = *(const uint4*)&Bp[(t * (N * 4) + (j * 8 + g) * 4 + qt) * 4];
        #pragma unroll
        for (int se = 0; se < 2; se++) {
            int s = 2 * t + se;
            if (s >= S) break;
            #pragma unroll
            for (int tm = 0; tm < TM; tm++) {
                const uint32_t* Ar = As + tm * 16 * sb2;
                uint32_t a0 = Ar[(g)     * sb2 + 8 * s + qt];
                uint32_t a2 = Ar[(g)     * sb2 + 8 * s + qt + 4];
                uint32_t a1 = Ar[(g + 8) * sb2 + 8 * s + qt];
                uint32_t a3 = Ar[(g + 8) * sb2 + 8 * s + qt + 4];
                #pragma unroll
                for (int j = 0; j < NTW; j++) {
                    uint32_t b0 = se ? bq[j].z : bq[j].x;
                    uint32_t b1 = se ? bq[j].w : bq[j].y;
                    mma16(c[tm][j], a0, a1, a2, a3, b0, b1);
                }
            }
        }
    }
}

// bf16 fragment pack index: element (k,n) of a KxN col-fragment weight.
DEV_INLINE int packB(int n, int k, int N) {
    int p = k >> 1, lo = k & 1;
    int qt = p & 3, half = (p >> 2) & 1, s = p >> 3;
    int t = s >> 1, se = s & 1;
    int u32i = (t * (N * 4) + n * 4 + qt) * 4 + se * 2 + half;
    return u32i * 2 + lo;
}

__global__ void pack_weights(const float* __restrict__ W_E, const float* __restrict__ W_G,
                             const float* __restrict__ W_Oe, const float* __restrict__ W_e1,
                             const float* __restrict__ W_e2)
{
    int i = blockIdx.x * 256 + threadIdx.x;
    if (i < 4096) {                       // WEG: K=64, N=64
        int k = i >> 6, n = i & 63;
        float v = n < 32 ? W_E[k * 32 + n] : W_G[k * 32 + n - 32];
        g_WEGb[packB(n, k, 64)] = __float2bfloat16(v);
    } else if (i < 6144) {                // WOe: K=32, N=64
        int j = i - 4096; int k = j >> 6, n = j & 63;
        g_WOeb[packB(n, k, 64)] = __float2bfloat16(W_Oe[j]);
    } else if (i < 14336) {               // We1: K=64, N=128
        int j = i - 6144; int k = j >> 7, n = j & 127;
        g_We1b[packB(n, k, 128)] = __float2bfloat16(W_e1[j]);
    } else if (i < 22528) {               // We2: K=128, N=64
        int j = i - 14336; int k = j >> 6, n = j & 63;
        g_We2b[packB(n, k, 64)] = __float2bfloat16(W_e2[j]);
    }
}

// ---------------- QK precompute: A_hat for all (b,l,m,h) -------------------
constexpr int QK_SMEM_BYTES = 64 * 256 * 4;   // 65536

__global__ void __launch_bounds__(256, 3) qk_kernel()
{
    extern __shared__ uint32_t ks[];   // [64][256] bf16x2 words
    int blk = blockIdx.x;
    int lt = blk & 15, mt = (blk >> 4) & 3, b = blk >> 6;
    int m0 = mt * 64;
    int tid = threadIdx.x;

    const uint4* Ksrc = (const uint4*)(g_kb + ((size_t)(b * 256) + m0) * 256);
    uint4* Kdst = (uint4*)ks;
    #pragma unroll
    for (int i = 0; i < 16; i++)
        Kdst[tid + i * 256] = Ksrc[tid + i * 256];
    __syncthreads();

    int h = tid & 31, grp = tid >> 5;
    #pragma unroll
    for (int li = 0; li < 2; li++) {
        int l  = lt * 16 + grp + li * 8;
        int bl = b * 256 + l;
        float q[16];
        const float* Qp = g_qkv + (size_t)bl * 1536 + h;
        #pragma unroll
        for (int d = 0; d < 16; d++) q[d] = Qp[d * 32];
        __nv_bfloat16* Adst = g_Ab + ((size_t)bl * 256 + m0) * 32 + h;
        for (int m = 0; m < 64; m++) {
            const uint32_t* Kp = ks + m * 256 + h;
            float a = 0.f;
            #pragma unroll
            for (int dp = 0; dp < 8; dp++) {
                float2 kv = __bfloat1622float2(*(const __nv_bfloat162*)&Kp[dp * 32]);
                a += q[2 * dp] * kv.x + q[2 * dp + 1] * kv.y;
            }
            Adst[(size_t)m * 32] = __float2bfloat16(a * 0.25f);
        }
    }
}

// ---------------- LayerNorm over 512, one block per row ----------------
__global__ void __launch_bounds__(128) ln512_kernel(
    const float* __restrict__ x, const float* __restrict__ g,
    const float* __restrict__ b, float* __restrict__ y)
{
    int row = blockIdx.x, tid = threadIdx.x;
    const float4* xr = (const float4*)(x + (size_t)row * 512);
    float4 v = xr[tid];
    float s  = v.x + v.y + v.z + v.w;
    float s2 = v.x*v.x + v.y*v.y + v.z*v.z + v.w*v.w;
    #pragma unroll
    for (int o = 16; o; o >>= 1) {
        s  += __shfl_xor_sync(0xffffffffu, s,  o);
        s2 += __shfl_xor_sync(0xffffffffu, s2, o);
    }
    __shared__ float aS[4], aS2[4];
    if ((tid & 31) == 0) { aS[tid >> 5] = s; aS2[tid >> 5] = s2; }
    __syncthreads();
    s  = aS[0] + aS[1] + aS[2] + aS[3];
    s2 = aS2[0] + aS2[1] + aS2[2] + aS2[3];
    float mean = s * (1.f / 512.f);
    float rstd = rsqrtf(s2 * (1.f / 512.f) - mean * mean + EPSc);
    int c = tid * 4;
    float4 gv = *(const float4*)(g + c);
    float4 bv = *(const float4*)(b + c);
    float4 o;
    o.x = (v.x - mean) * rstd * gv.x + bv.x;
    o.y = (v.y - mean) * rstd * gv.y + bv.y;
    o.z = (v.z - mean) * rstd * gv.z + bv.z;
    o.w = (v.w - mean) * rstd * gv.w + bv.w;
    ((float4*)(y + (size_t)row * 512))[tid] = o;
}

// ---------------- tf32 tensor GEMM (h-path; MODE 3 = QKV with K/V bf16 pack) --
constexpr int TG_SMEM_BYTES = (128 * 68 + 64 * 72) * 4;   // 53248
template<int MODE>
__global__ void __launch_bounds__(256) tgemm_tf(
    const float* __restrict__ A, const float* __restrict__ B, float* __restrict__ C,
    const float* __restrict__ bias, const float* __restrict__ res,
    int M, int N, int K)
{
    extern __shared__ float ts[];
    float* As = ts;              // 128 x 68
    float* Bs = ts + 128 * 68;   // 64 x 72
    int tid = threadIdx.x;
    int row0 = blockIdx.y * 128, col0 = blockIdx.x * 64;
    int w = tid >> 5;
    int g = (tid & 31) >> 2, qt = tid & 3;
    float acc[8][4] = {};

    for (int k0 = 0; k0 < K; k0 += 64) {
        #pragma unroll
        for (int i = 0; i < 8; i++) {
            int idx = tid + i * 256;
            int r = idx >> 4, c4 = idx & 15;
            float4 v = *(const float4*)&A[(size_t)(row0 + r) * K + k0 + c4 * 4];
            float4 t;
            t.x = to_tf32(v.x); t.y = to_tf32(v.y); t.z = to_tf32(v.z); t.w = to_tf32(v.w);
            *(float4*)&As[r * 68 + c4 * 4] = t;
        }
        #pragma unroll
        for (int i = 0; i < 4; i++) {
            int idx = tid + i * 256;
            int r = idx >> 4, c4 = idx & 15;
            float4 v = *(const float4*)&B[(size_t)(k0 + r) * N + col0 + c4 * 4];
            float4 t;
            t.x = to_tf32(v.x); t.y = to_tf32(v.y); t.z = to_tf32(v.z); t.w = to_tf32(v.w);
            *(float4*)&Bs[r * 72 + c4 * 4] = t;
        }
        __syncthreads();
        wgemm<8, 8>(acc, As + w * 16 * 68, 68, Bs, 72, g, qt);
        __syncthreads();
    }
    if (MODE == 3 && col0 >= 512) {
        // K/V tile: pack (c, c+32) bf16 pairs to g_kb / g_vb; no fp32 store.
        bool isK = (col0 < 1024);
        uint32_t* dstBase = (uint32_t*)(isK ? g_kb : g_vb);
        int obase = col0 - (isK ? 512 : 1024);
        #pragma unroll
        for (int j = 0; j < 4; j++) {
            int c = col0 + j * 8 + 2 * qt;
            int o = obase + j * 8 + 2 * qt;
            int dp = o >> 6, hh = o & 31;
            float b00 = bias[c],      b01 = bias[c + 1];
            float b10 = bias[c + 32], b11 = bias[c + 33];
            #pragma unroll
            for (int hf = 0; hf < 2; hf++) {
                int r = row0 + w * 16 + g + hf * 8;
                uint32_t* d = dstBase + (size_t)r * 256 + dp * 32 + hh;
                d[0] = packbf(acc[j][hf * 2 + 0] + b00, acc[j + 4][hf * 2 + 0] + b10);
                d[1] = packbf(acc[j][hf * 2 + 1] + b01, acc[j + 4][hf * 2 + 1] + b11);
            }
        }
        return;
    }
    #pragma unroll
    for (int j = 0; j < 8; j++) {
        int col = col0 + j * 8 + 2 * qt;
        #pragma unroll
        for (int hf = 0; hf < 2; hf++) {
            int r = row0 + w * 16 + g + hf * 8;
            float v0 = acc[j][hf * 2 + 0] + bias[col];
            float v1 = acc[j][hf * 2 + 1] + bias[col + 1];
            if (MODE == 1) {
                float2 rv = *(const float2*)&res[(size_t)r * N + col];
                v0 += rv.x; v1 += rv.y;
            }
            if (MODE == 2) {
                v0 = v0 > 0.f ? v0 : __expf(v0) - 1.f;
                v1 = v1 > 0.f ? v1 : __expf(v1) - 1.f;
            }
            float2 ov; ov.x = v0; ov.y = v1;
            *(float2*)&C[(size_t)r * N + col] = ov;
        }
    }
}

// LN of 64 rows x 64 cols: fp32 src (stride sstr) -> bf16x2 dst (dsb2 u32/row).
DEV_INLINE void ln64b(const float* __restrict__ src, int sstr, uint32_t* __restrict__ dst,
                      int dsb2, const float* __restrict__ gam,
                      const float* __restrict__ bet, int tid)
{
    int r = tid >> 2, sub = tid & 3;
    const float* p = src + r * sstr + sub * 16;
    float x[16]; float s = 0.f, s2 = 0.f;
    #pragma unroll
    for (int i = 0; i < 16; i += 4) {
        float4 v = *(const float4*)(p + i);
        x[i] = v.x; x[i+1] = v.y; x[i+2] = v.z; x[i+3] = v.w;
    }
    #pragma unroll
    for (int i = 0; i < 16; i++) { s += x[i]; s2 += x[i] * x[i]; }
    s  += __shfl_xor_sync(0xffffffffu, s, 1);  s  += __shfl_xor_sync(0xffffffffu, s, 2);
    s2 += __shfl_xor_sync(0xffffffffu, s2, 1); s2 += __shfl_xor_sync(0xffffffffu, s2, 2);
    float mean = s * (1.f / 64.f);
    float rstd = rsqrtf(s2 * (1.f / 64.f) - mean * mean + EPSc);
    uint32_t* d = dst + r * dsb2 + sub * 8;
    #pragma unroll
    for (int i = 0; i < 16; i += 2) {
        int c = sub * 16 + i;
        float y0 = (x[i]     - mean) * rstd * gam[c]     + bet[c];
        float y1 = (x[i + 1] - mean) * rstd * gam[c + 1] + bet[c + 1];
        d[i >> 1] = packbf(y0, y1);
    }
}

// Fused: load e tile from global, keep fp32 copy in sX, LN -> bf16x2 sXb.
DEV_INLINE void ln64g(const float* __restrict__ eg, float* __restrict__ sX,
                      uint32_t* __restrict__ sXb,
                      const float* __restrict__ gam, const float* __restrict__ bet, int tid)
{
    int r = tid >> 2, sub = tid & 3;
    const float* p = eg + r * 64 + sub * 16;
    float* q = sX + r * 68 + sub * 16;
    float x[16]; float s = 0.f, s2 = 0.f;
    #pragma unroll
    for (int i = 0; i < 16; i += 4) {
        float4 v = *(const float4*)(p + i);
        *(float4*)(q + i) = v;
        x[i] = v.x; x[i+1] = v.y; x[i+2] = v.z; x[i+3] = v.w;
    }
    #pragma unroll
    for (int i = 0; i < 16; i++) { s += x[i]; s2 += x[i] * x[i]; }
    s  += __shfl_xor_sync(0xffffffffu, s, 1);  s  += __shfl_xor_sync(0xffffffffu, s, 2);
    s2 += __shfl_xor_sync(0xffffffffu, s2, 1); s2 += __shfl_xor_sync(0xffffffffu, s2, 2);
    float mean = s * (1.f / 64.f);
    float rstd = rsqrtf(s2 * (1.f / 64.f) - mean * mean + EPSc);
    uint32_t* d = sXb + r * 36 + sub * 8;
    #pragma unroll
    for (int i = 0; i < 16; i += 2) {
        int c = sub * 16 + i;
        float y0 = (x[i]     - mean) * rstd * gam[c]     + bet[c];
        float y1 = (x[i + 1] - mean) * rstd * gam[c + 1] + bet[c + 1];
        d[i >> 1] = packbf(y0, y1);
    }
}

// ---------------- edge pipeline: 64 rows/CTA, 256 threads, 4 CTA/SM ------------
constexpr int EA_SMEM_BYTES = (4352 + 2304 + 1280 + 4352) * 4;  // 49152

__global__ void __launch_bounds__(256, 4) ea_kernel(
    const float* __restrict__ e, const float* __restrict__ mask,
    const float* __restrict__ lng, const float* __restrict__ lnb,
    const float* __restrict__ flg, const float* __restrict__ flb,
    const float* __restrict__ b_E,  const float* __restrict__ b_G,
    const float* __restrict__ b_Oe, const float* __restrict__ b_e1,
    const float* __restrict__ b_e2,
    float* __restrict__ e_out)
{
    extern __shared__ float sm[];
    float*    sX  = sm;                          // 64 x 68 fp32 (e, then e2)
    uint32_t* sXb = (uint32_t*)(sm + 4352);      // 64 x 36 u32 (eln/eff bf16x2)
    uint32_t* sAb = (uint32_t*)(sm + 6656);      // 64 x 20 u32 (H bf16x2)
    uint32_t* sTb = (uint32_t*)(sm + 7936);      // 64 x 68 u32 (T bf16x2)

    int tid = threadIdx.x;
    int blk = blockIdx.x;
    int bl  = blk >> 2, quad = blk & 3;
    int m0  = quad * 64;
    size_t R0 = (size_t)bl * 256 + m0;

    int w   = tid >> 5;
    int wm2 = w >> 2, wn = w & 3;       // rows wm2*32, col quarter wn
    int g   = (tid & 31) >> 2, qt = tid & 3;
    int rowb = wm2 * 32;

    const uint32_t* WEGu = (const uint32_t*)g_WEGb;
    const uint32_t* WOeu = (const uint32_t*)g_WOeb;
    const uint32_t* We1u = (const uint32_t*)g_We1b;
    const uint32_t* We2u = (const uint32_t*)g_We2b;

    // Pa: load e + LN(e) -> sX (fp32 copy) and sXb (bf16)
    ln64g(e + R0 * 64, sX, sXb, lng, lnb, tid);
    __syncthreads();

    // Pb: GEMM1 (E|G)
    float c1[2][2][4] = {};
    wgemm_b<2, 2, 4, 64>(c1, sXb + rowb * 36, 36, WEGu + wn * 256, g, qt);
    __syncthreads();

    // Pc: epilogue — wn<2: H (A from g_Ab, cols 0..31) -> g_Hb + sAb ;
    //                wn>=2: gate -> g_gateb
    {
        #pragma unroll
        for (int tm = 0; tm < 2; tm++) {
            float mk0 = mask[(size_t)bl * 256 + m0 + rowb + tm * 16 + g];
            float mk1 = mask[(size_t)bl * 256 + m0 + rowb + tm * 16 + g + 8];
            #pragma unroll
            for (int j = 0; j < 2; j++) {
                int colg = wn * 16 + j * 8 + 2 * qt;
                if (wn < 2) {
                    int col = colg;
                    float bv0 = b_E[col], bv1 = b_E[col + 1];
                    #pragma unroll
                    for (int hf = 0; hf < 2; hf++) {
                        int r = rowb + tm * 16 + g + hf * 8;
                        uint32_t aw = ((const uint32_t*)g_Ab)[(R0 + r) * 16 + (col >> 1)];
                        float2 Af = __bfloat1622float2(*(__nv_bfloat162*)&aw);
                        float H0 = fminf(fmaxf(Af.x, -5.f), 5.f) + c1[tm][j][hf * 2 + 0] + bv0;
                        float H1 = fminf(fmaxf(Af.y, -5.f), 5.f) + c1[tm][j][hf * 2 + 1] + bv1;
                        float mk = hf ? mk1 : mk0;
                        g_Hb[(R0 + r) * 16 + (col >> 1)] = packbf(H0 + mk, H1 + mk);
                        sAb[r * 20 + (col >> 1)] = packbf(H0, H1);
                    }
                } else {
                    int col = colg - 32;
                    float bv0 = b_G[col], bv1 = b_G[col + 1];
                    #pragma unroll
                    for (int hf = 0; hf < 2; hf++) {
                        int r = rowb + tm * 16 + g + hf * 8;
                        float mk = hf ? mk1 : mk0;
                        float g0 = 1.f / (1.f + __expf(-(c1[tm][j][hf * 2 + 0] + bv0 + mk)));
                        float g1 = 1.f / (1.f + __expf(-(c1[tm][j][hf * 2 + 1] + bv1 + mk)));
                        g_gateb[(R0 + r) * 16 + (col >> 1)] = packbf(g0, g1);
                    }
                }
            }
        }
    }
    __syncthreads();

    // Pd: GEMM2  e2 = H @ W_Oe + b + e(sX)   (sX overwrite; no reg copy)
    {
        float c2[2][2][4] = {};
        wgemm_b<2, 2, 2, 64>(c2, sAb + rowb * 20, 20, WOeu + wn * 256, g, qt);
        #pragma unroll
        for (int tm = 0; tm < 2; tm++)
            #pragma unroll
            for (int j = 0; j < 2; j++) {
                int col = wn * 16 + j * 8 + 2 * qt;
                float bo0 = b_Oe[col], bo1 = b_Oe[col + 1];
                #pragma unroll
                for (int hf = 0; hf < 2; hf++) {
                    int r = rowb + tm * 16 + g + hf * 8;
                    sX[r * 68 + col]     = c2[tm][j][hf * 2 + 0] + bo0 + sX[r * 68 + col];
                    sX[r * 68 + col + 1] = c2[tm][j][hf * 2 + 1] + bo1 + sX[r * 68 + col + 1];
                }
            }
    }
    __syncthreads();

    // Pe: LN(e2) -> sXb (bf16 eff)
    ln64b(sX, 68, sXb, 36, flg, flb, tid);
    __syncthreads();

    // Pf: GEMM3  T = elu(eff @ W_e1 + b) -> sTb, two 16-col halves per warp
    #pragma unroll
    for (int half = 0; half < 2; half++) {
        float c3[2][2][4] = {};
        int cb = wn * 32 + half * 16;
        wgemm_b<2, 2, 4, 128>(c3, sXb + rowb * 36, 36, We1u + cb * 16, g, qt);
        #pragma unroll
        for (int tm = 0; tm < 2; tm++)
            #pragma unroll
            for (int j = 0; j < 2; j++) {
                int col = cb + j * 8 + 2 * qt;
                float bb0 = b_e1[col], bb1 = b_e1[col + 1];
                #pragma unroll
                for (int hf = 0; hf < 2; hf++) {
                    int r = rowb + tm * 16 + g + hf * 8;
                    float v0 = c3[tm][j][hf * 2 + 0] + bb0;
                    float v1 = c3[tm][j][hf * 2 + 1] + bb1;
                    v0 = v0 > 0.f ? v0 : __expf(v0) - 1.f;
                    v1 = v1 > 0.f ? v1 : __expf(v1) - 1.f;
                    sTb[r * 68 + (col >> 1)] = packbf(v0, v1);
                }
            }
    }
    __syncthreads();

    // Pg: GEMM4  e_out = T @ W_e2 + b + e2(sX)
    {
        float c4[2][2][4] = {};
        wgemm_b<2, 2, 8, 64>(c4, sTb + rowb * 68, 68, We2u + wn * 256, g, qt);
        #pragma unroll
        for (int tm = 0; tm < 2; tm++)
            #pragma unroll
            for (int j = 0; j < 2; j++) {
                int col = wn * 16 + j * 8 + 2 * qt;
                float bz0 = b_e2[col], bz1 = b_e2[col + 1];
                #pragma unroll
                for (int hf = 0; hf < 2; hf++) {
                    int r = rowb + tm * 16 + g + hf * 8;
                    float2 ov;
                    ov.x = c4[tm][j][hf * 2 + 0] + bz0 + sX[r * 68 + col];
                    ov.y = c4[tm][j][hf * 2 + 1] + bz1 + sX[r * 68 + col + 1];
                    *(float2*)&e_out[(R0 + r) * 64 + col] = ov;
                }
            }
    }
}

// ---------------- softmax + gated V accumulation: one block per (b,l) ----------
__global__ void __launch_bounds__(256) eb_kernel()
{
    __shared__ float sH[256 * 36];
    __shared__ float sRed[256];
    __shared__ float sRed2[256];

    int tid = threadIdx.x;
    int bl  = blockIdx.x;
    int b   = bl >> 8;

    const uint4* Hg = (const uint4*)(g_Hb + (size_t)bl * 4096);
    #pragma unroll
    for (int i = 0; i < 4; i++) {
        int idx = tid + i * 256;          // 1024 uint4
        int m = idx >> 2, q = idx & 3;
        uint4 hv = Hg[idx];
        uint32_t ws[4] = {hv.x, hv.y, hv.z, hv.w};
        #pragma unroll
        for (int j = 0; j < 4; j++) {
            float2 f = __bfloat1622float2(*(__nv_bfloat162*)&ws[j]);
            sH[m * 36 + q * 8 + 2 * j]     = f.x;
            sH[m * 36 + q * 8 + 2 * j + 1] = f.y;
        }
    }
    __syncthreads();

    int h = tid & 31, grp = tid >> 5;
    float pmax = -1e30f;
    for (int mm = 0; mm < 32; mm++) {
        int m = grp * 32 + mm;
        pmax = fmaxf(pmax, sH[m * 36 + h]);
    }
    sRed[grp * 32 + h] = pmax;
    __syncthreads();
    float M = -1e30f;
    #pragma unroll
    for (int gg = 0; gg < 8; gg++) M = fmaxf(M, sRed[gg * 32 + h]);

    const uint32_t* gateR = g_gateb + (size_t)bl * 4096;
    float ssum = 0.f;
    for (int mm = 0; mm < 32; mm++) {
        int m = grp * 32 + mm;
        float wv = __expf(sH[m * 36 + h] - M);
        ssum += wv;
        uint32_t gw = gateR[m * 16 + (h >> 1)];
        float2 gf = __bfloat1622float2(*(__nv_bfloat162*)&gw);
        float gate = (h & 1) ? gf.y : gf.x;
        sH[m * 36 + h] = wv * gate;
    }
    sRed2[grp * 32 + h] = ssum;
    __syncthreads();
    float S = 0.f;
    #pragma unroll
    for (int gg = 0; gg < 8; gg++) S += sRed2[gg * 32 + h];
    float inv = 1.f / S;

    float a0 = 0.f, a1 = 0.f;
    const __nv_bfloat162* Vb = g_vb + (size_t)(b * 256) * 256 + grp * 32 + h;
    #pragma unroll 8
    for (int m = 0; m < 256; m++) {
        float wv = sH[m * 36 + h];
        float2 vv = __bfloat1622float2(Vb[(size_t)m * 256]);
        a0 += wv * vv.x;
        a1 += wv * vv.y;
    }
    int k0 = grp * 2;
    g_vatt[(size_t)bl * 512 + k0 * 32 + h]       = a0 * inv;
    g_vatt[(size_t)bl * 512 + (k0 + 1) * 32 + h] = a1 * inv;
}

// ---------------- launch ----------------
extern "C" void kernel_launch(void* const* d_in, const int* in_sizes, int n_in,
                              void* d_out, int out_size)
{
    const float* h         = (const float*)d_in[0];
    const float* e         = (const float*)d_in[1];
    const float* mask      = (const float*)d_in[2];
    const float* ln_h_g    = (const float*)d_in[3];
    const float* ln_h_b    = (const float*)d_in[4];
    const float* ln_e_g    = (const float*)d_in[5];
    const float* ln_e_b    = (const float*)d_in[6];
    const float* ffn_ln_h_g= (const float*)d_in[7];
    const float* ffn_ln_h_b= (const float*)d_in[8];
    const float* ffn_ln_e_g= (const float*)d_in[9];
    const float* ffn_ln_e_b= (const float*)d_in[10];
    const float* W_qkv     = (const float*)d_in[11];
    const float* b_qkv     = (const float*)d_in[12];
    const float* W_E       = (const float*)d_in[13];
    const float* b_E       = (const float*)d_in[14];
    const float* W_G       = (const float*)d_in[15];
    const float* b_G       = (const float*)d_in[16];
    const float* W_Oh      = (const float*)d_in[17];
    const float* b_Oh      = (const float*)d_in[18];
    const float* W_h1      = (const float*)d_in[19];
    const float* b_h1      = (const float*)d_in[20];
    const float* W_h2      = (const float*)d_in[21];
    const float* b_h2      = (const float*)d_in[22];
    const float* W_Oe      = (const float*)d_in[23];
    const float* b_Oe      = (const float*)d_in[24];
    const float* W_e1      = (const float*)d_in[25];
    const float* b_e1      = (const float*)d_in[26];
    const float* W_e2      = (const float*)d_in[27];
    const float* b_e2      = (const float*)d_in[28];

    float* h_out = (float*)d_out;
    float* e_out = (float*)d_out + (size_t)ROWS * DNn;

    float *p_hln, *p_qkv, *p_vatt, *p_h2, *p_hff, *p_t;
    cudaGetSymbolAddress((void**)&p_hln,  g_hln);
    cudaGetSymbolAddress((void**)&p_qkv,  g_qkv);
    cudaGetSymbolAddress((void**)&p_vatt, g_vatt);
    cudaGetSymbolAddress((void**)&p_h2,   g_h2);
    cudaGetSymbolAddress((void**)&p_hff,  g_hff);
    cudaGetSymbolAddress((void**)&p_t,    g_t);

    cudaFuncSetAttribute(ea_kernel, cudaFuncAttributeMaxDynamicSharedMemorySize,
                         EA_SMEM_BYTES);
    cudaFuncSetAttribute(qk_kernel, cudaFuncAttributeMaxDynamicSharedMemorySize,
                         QK_SMEM_BYTES);
    cudaFuncSetAttribute(tgemm_tf<1>, cudaFuncAttributeMaxDynamicSharedMemorySize,
                         TG_SMEM_BYTES);
    cudaFuncSetAttribute(tgemm_tf<2>, cudaFuncAttributeMaxDynamicSharedMemorySize,
                         TG_SMEM_BYTES);
    cudaFuncSetAttribute(tgemm_tf<3>, cudaFuncAttributeMaxDynamicSharedMemorySize,
                         TG_SMEM_BYTES);

    // 0) pack edge weights (bf16 fragments)
    pack_weights<<<88, 256>>>(W_E, W_G, W_Oe, W_e1, W_e2);
    // 1) h_ln
    ln512_kernel<<<ROWS, 128>>>(h, ln_h_g, ln_h_b, p_hln);
    // 2) QKV (tf32); Q -> g_qkv fp32, K/V -> g_kb/g_vb bf16 (fused pack)
    tgemm_tf<3><<<dim3(1536/64, ROWS/128), 256, TG_SMEM_BYTES>>>(p_hln, W_qkv, p_qkv,
                                                  b_qkv, nullptr, ROWS, 1536, 512);
    // 2.6) QK precompute: A_hat (K tile reused across 16 l's)
    qk_kernel<<<Bn * 4 * 16, 256, QK_SMEM_BYTES>>>();
    // 3) edge pipeline (writes e_out, g_Hb(+mask), g_gateb)
    ea_kernel<<<ROWS * 4, 256, EA_SMEM_BYTES>>>(e, mask, ln_e_g, ln_e_b,
        ffn_ln_e_g, ffn_ln_e_b, b_E, b_G, b_Oe, b_e1, b_e2, e_out);
    // 4) softmax + gated V accumulation (writes g_vatt)
    eb_kernel<<<ROWS, 256>>>();
    // 5) h2 = V_att @ W_Oh + b + h
    tgemm_tf<1><<<dim3(512/64, ROWS/128), 256, TG_SMEM_BYTES>>>(p_vatt, W_Oh, p_h2,
                                                 b_Oh, h, ROWS, 512, 512);
    // 6) h_ff = LN(h2)
    ln512_kernel<<<ROWS, 128>>>(p_h2, ffn_ln_h_g, ffn_ln_h_b, p_hff);
    // 7) t = elu(h_ff @ W_h1 + b)
    tgemm_tf<2><<<dim3(1024/64, ROWS/128), 256, TG_SMEM_BYTES>>>(p_hff, W_h1, p_t,
                                                  b_h1, nullptr, ROWS, 1024, 512);
    // 8) h_out = t @ W_h2 + b + h2
    tgemm_tf<1><<<dim3(512/64, ROWS/128), 256, TG_SMEM_BYTES>>>(p_t, W_h2, h_out,
                                                 b_h2, p_h2, ROWS, 512, 1024);
}

// round 14
// speedup vs baseline: 1.1534x; 1.0506x over previous
#include <cuda_runtime.h>
#include <cuda_bf16.h>
#include <math.h>
#include <stdint.h>

#define DEV_INLINE __device__ __forceinline__

constexpr int Bn = 32, Ln = 256, DNn = 512;
constexpr int ROWS = Bn * Ln;            // 8192 (b,l) rows
constexpr int EROWS = ROWS * Ln;         // 2,097,152 edge rows
constexpr int FNn = 1024;
constexpr float EPSc = 1e-5f;

// ---------------- device scratch ----------------
__device__ float g_hln[ROWS * DNn];
__device__ float g_qkv[ROWS * 3 * DNn];       // only Q region (cols 0..511) written
__device__ float g_vatt[ROWS * DNn];
__device__ float g_h2[ROWS * DNn];
__device__ float g_hff[ROWS * DNn];
__device__ float g_t[ROWS * FNn];
__device__ uint32_t g_Hb[(size_t)EROWS * 16];     // H_hat + mask, bf16x2
__device__ uint32_t g_gateb[(size_t)EROWS * 16];  // sigmoid(G+mask), bf16x2
__device__ __nv_bfloat16 g_Ab[(size_t)EROWS * 32];// A_hat (scaled), bf16
// bf16 fragment-packed edge weights (see packB); bf16 K and V
__device__ __nv_bfloat16 g_WEGb[64 * 64];
__device__ __nv_bfloat16 g_WOeb[32 * 64];
__device__ __nv_bfloat16 g_We1b[64 * 128];
__device__ __nv_bfloat16 g_We2b[128 * 64];
__device__ __nv_bfloat162 g_kb[(size_t)ROWS * 256];   // [(row)*256 + dp*32 + h]
__device__ __nv_bfloat162 g_vb[(size_t)ROWS * 256];   // [(row)*256 + kp*32 + h]

DEV_INLINE uint32_t packbf(float a, float b) {
    __nv_bfloat162 h2 = __floats2bfloat162_rn(a, b);
    return *(uint32_t*)&h2;
}

DEV_INLINE float to_tf32(float x) {
    float y;
    asm("cvt.rna.tf32.f32 %0, %1;" : "=f"(y) : "f"(x));
    return y;
}

DEV_INLINE void mma8(float c[4], uint32_t a0, uint32_t a1, uint32_t a2, uint32_t a3,
                     uint32_t b0, uint32_t b1)
{
    asm volatile(
        "mma.sync.aligned.m16n8k8.row.col.f32.tf32.tf32.f32 "
        "{%0,%1,%2,%3},{%4,%5,%6,%7},{%8,%9},{%0,%1,%2,%3};"
        : "+f"(c[0]), "+f"(c[1]), "+f"(c[2]), "+f"(c[3])
        : "r"(a0), "r"(a1), "r"(a2), "r"(a3), "r"(b0), "r"(b1));
}

DEV_INLINE void mma16(float c[4], uint32_t a0, uint32_t a1, uint32_t a2, uint32_t a3,
                      uint32_t b0, uint32_t b1)
{
    asm volatile(
        "mma.sync.aligned.m16n8k16.row.col.f32.bf16.bf16.f32 "
        "{%0,%1,%2,%3},{%4,%5,%6,%7},{%8,%9},{%0,%1,%2,%3};"
        : "+f"(c[0]), "+f"(c[1]), "+f"(c[2]), "+f"(c[3])
        : "r"(a0), "r"(a1), "r"(a2), "r"(a3), "r"(b0), "r"(b1));
}

// smem-B tf32 warp GEMM (h-path)
template<int NTW, int KS>
DEV_INLINE void wgemm(float c[NTW][4], const float* __restrict__ Arow, int lda,
                      const float* __restrict__ Bcol, int ldb, int g, int qt)
{
    #pragma unroll
    for (int ks = 0; ks < KS; ks++) {
        int k = ks * 8;
        uint32_t a0 = __float_as_uint(Arow[(g)     * lda + k + qt]);
        uint32_t a1 = __float_as_uint(Arow[(g + 8) * lda + k + qt]);
        uint32_t a2 = __float_as_uint(Arow[(g)     * lda + k + qt + 4]);
        uint32_t a3 = __float_as_uint(Arow[(g + 8) * lda + k + qt + 4]);
        #pragma unroll
        for (int j = 0; j < NTW; j++) {
            uint32_t b0 = __float_as_uint(Bcol[(k + qt)     * ldb + j * 8 + g]);
            uint32_t b1 = __float_as_uint(Bcol[(k + qt + 4) * ldb + j * 8 + g]);
            mma8(c[j], a0, a1, a2, a3, b0, b1);
        }
    }
}

// bf16 warp GEMM, m16n8k16. A in smem as u32 (bf16x2), sb2 = u32 words per row.
template<int TM, int NTW, int S, int N>
DEV_INLINE void wgemm_b(float c[TM][NTW][4], const uint32_t* __restrict__ As, int sb2,
                        const uint32_t* __restrict__ Bp, int g, int qt)
{
    #pragma unroll
    for (int t = 0; t < (S + 1) / 2; t++) {
        uint4 bq[NTW];
        #pragma unroll
        for (int j = 0; j < NTW; j++)
            bq[j] = *(const uint4*)&Bp[(t * (N * 4) + (j * 8 + g) * 4 + qt) * 4];
        #pragma unroll
        for (int se = 0; se < 2; se++) {
            int s = 2 * t + se;
            if (s >= S) break;
            #pragma unroll
            for (int tm = 0; tm < TM; tm++) {
                const uint32_t* Ar = As + tm * 16 * sb2;
                uint32_t a0 = Ar[(g)     * sb2 + 8 * s + qt];
                uint32_t a2 = Ar[(g)     * sb2 + 8 * s + qt + 4];
                uint32_t a1 = Ar[(g + 8) * sb2 + 8 * s + qt];
                uint32_t a3 = Ar[(g + 8) * sb2 + 8 * s + qt + 4];
                #pragma unroll
                for (int j = 0; j < NTW; j++) {
                    uint32_t b0 = se ? bq[j].z : bq[j].x;
                    uint32_t b1 = se ? bq[j].w : bq[j].y;
                    mma16(c[tm][j], a0, a1, a2, a3, b0, b1);
                }
            }
        }
    }
}

// bf16 fragment pack index: element (k,n) of a KxN col-fragment weight.
DEV_INLINE int packB(int n, int k, int N) {
    int p = k >> 1, lo = k & 1;
    int qt = p & 3, half = (p >> 2) & 1, s = p >> 3;
    int t = s >> 1, se = s & 1;
    int u32i = (t * (N * 4) + n * 4 + qt) * 4 + se * 2 + half;
    return u32i * 2 + lo;
}

__global__ void pack_weights(const float* __restrict__ W_E, const float* __restrict__ W_G,
                             const float* __restrict__ W_Oe, const float* __restrict__ W_e1,
                             const float* __restrict__ W_e2)
{
    int i = blockIdx.x * 256 + threadIdx.x;
    if (i < 4096) {                       // WEG: K=64, N=64
        int k = i >> 6, n = i & 63;
        float v = n < 32 ? W_E[k * 32 + n] : W_G[k * 32 + n - 32];
        g_WEGb[packB(n, k, 64)] = __float2bfloat16(v);
    } else if (i < 6144) {                // WOe: K=32, N=64
        int j = i - 4096; int k = j >> 6, n = j & 63;
        g_WOeb[packB(n, k, 64)] = __float2bfloat16(W_Oe[j]);
    } else if (i < 14336) {               // We1: K=64, N=128
        int j = i - 6144; int k = j >> 7, n = j & 127;
        g_We1b[packB(n, k, 128)] = __float2bfloat16(W_e1[j]);
    } else if (i < 22528) {               // We2: K=128, N=64
        int j = i - 14336; int k = j >> 6, n = j & 63;
        g_We2b[packB(n, k, 64)] = __float2bfloat16(W_e2[j]);
    }
}

// ---------------- QK precompute: A_hat, 4 l's per thread --------------------
// CTA = (b, m-tile 64, l-tile 32). K tile staged once, unpacked once per m
// and reused by 4 l's per thread (vs 1 before): ~1.8x fewer issue slots.
constexpr int QK_SMEM_BYTES = 64 * 256 * 4;   // 65536

__global__ void __launch_bounds__(256, 2) qk_kernel()
{
    extern __shared__ uint32_t ks[];   // [64][256] bf16x2 words
    int blk = blockIdx.x;
    int lt = blk & 7, mt = (blk >> 3) & 3, b = blk >> 5;
    int m0 = mt * 64, l0 = lt * 32;
    int tid = threadIdx.x;

    // stage K tile (64 rows x 1KB)
    const uint4* Ksrc = (const uint4*)(g_kb + ((size_t)(b * 256) + m0) * 256);
    uint4* Kdst = (uint4*)ks;
    #pragma unroll
    for (int i = 0; i < 16; i++)
        Kdst[tid + i * 256] = Ksrc[tid + i * 256];
    __syncthreads();

    int h = tid & 31, lg = tid >> 5;     // lg = 0..7, 4 l's each
    int l = l0 + lg * 4;
    int bl = b * 256 + l;

    float q[4][16];
    #pragma unroll
    for (int li = 0; li < 4; li++) {
        const float* Qp = g_qkv + (size_t)(bl + li) * 1536 + h;
        #pragma unroll
        for (int d = 0; d < 16; d++) q[li][d] = Qp[d * 32];
    }

    __nv_bfloat16* Ad0 = g_Ab + ((size_t)(bl + 0) * 256 + m0) * 32 + h;
    __nv_bfloat16* Ad1 = g_Ab + ((size_t)(bl + 1) * 256 + m0) * 32 + h;
    __nv_bfloat16* Ad2 = g_Ab + ((size_t)(bl + 2) * 256 + m0) * 32 + h;
    __nv_bfloat16* Ad3 = g_Ab + ((size_t)(bl + 3) * 256 + m0) * 32 + h;

    #pragma unroll 2
    for (int m = 0; m < 64; m++) {
        const uint32_t* Kp = ks + m * 256 + h;
        float kf[16];
        #pragma unroll
        for (int dp = 0; dp < 8; dp++) {
            uint32_t wv = Kp[dp * 32];
            kf[2 * dp]     = __uint_as_float(wv << 16);
            kf[2 * dp + 1] = __uint_as_float(wv & 0xffff0000u);
        }
        float a0 = 0.f, a1 = 0.f, a2 = 0.f, a3 = 0.f;
        #pragma unroll
        for (int d = 0; d < 16; d++) {
            a0 += q[0][d] * kf[d];
            a1 += q[1][d] * kf[d];
            a2 += q[2][d] * kf[d];
            a3 += q[3][d] * kf[d];
        }
        Ad0[(size_t)m * 32] = __float2bfloat16(a0 * 0.25f);
        Ad1[(size_t)m * 32] = __float2bfloat16(a1 * 0.25f);
        Ad2[(size_t)m * 32] = __float2bfloat16(a2 * 0.25f);
        Ad3[(size_t)m * 32] = __float2bfloat16(a3 * 0.25f);
    }
}

// ---------------- LayerNorm over 512, one block per row ----------------
__global__ void __launch_bounds__(128) ln512_kernel(
    const float* __restrict__ x, const float* __restrict__ g,
    const float* __restrict__ b, float* __restrict__ y)
{
    int row = blockIdx.x, tid = threadIdx.x;
    const float4* xr = (const float4*)(x + (size_t)row * 512);
    float4 v = xr[tid];
    float s  = v.x + v.y + v.z + v.w;
    float s2 = v.x*v.x + v.y*v.y + v.z*v.z + v.w*v.w;
    #pragma unroll
    for (int o = 16; o; o >>= 1) {
        s  += __shfl_xor_sync(0xffffffffu, s,  o);
        s2 += __shfl_xor_sync(0xffffffffu, s2, o);
    }
    __shared__ float aS[4], aS2[4];
    if ((tid & 31) == 0) { aS[tid >> 5] = s; aS2[tid >> 5] = s2; }
    __syncthreads();
    s  = aS[0] + aS[1] + aS[2] + aS[3];
    s2 = aS2[0] + aS2[1] + aS2[2] + aS2[3];
    float mean = s * (1.f / 512.f);
    float rstd = rsqrtf(s2 * (1.f / 512.f) - mean * mean + EPSc);
    int c = tid * 4;
    float4 gv = *(const float4*)(g + c);
    float4 bv = *(const float4*)(b + c);
    float4 o;
    o.x = (v.x - mean) * rstd * gv.x + bv.x;
    o.y = (v.y - mean) * rstd * gv.y + bv.y;
    o.z = (v.z - mean) * rstd * gv.z + bv.z;
    o.w = (v.w - mean) * rstd * gv.w + bv.w;
    ((float4*)(y + (size_t)row * 512))[tid] = o;
}

// ---------------- tf32 tensor GEMM (h-path; MODE 3 = QKV with K/V bf16 pack) --
constexpr int TG_SMEM_BYTES = (128 * 68 + 64 * 72) * 4;   // 53248
template<int MODE>
__global__ void __launch_bounds__(256) tgemm_tf(
    const float* __restrict__ A, const float* __restrict__ B, float* __restrict__ C,
    const float* __restrict__ bias, const float* __restrict__ res,
    int M, int N, int K)
{
    extern __shared__ float ts[];
    float* As = ts;              // 128 x 68
    float* Bs = ts + 128 * 68;   // 64 x 72
    int tid = threadIdx.x;
    int row0 = blockIdx.y * 128, col0 = blockIdx.x * 64;
    int w = tid >> 5;
    int g = (tid & 31) >> 2, qt = tid & 3;
    float acc[8][4] = {};

    for (int k0 = 0; k0 < K; k0 += 64) {
        #pragma unroll
        for (int i = 0; i < 8; i++) {
            int idx = tid + i * 256;
            int r = idx >> 4, c4 = idx & 15;
            float4 v = *(const float4*)&A[(size_t)(row0 + r) * K + k0 + c4 * 4];
            float4 t;
            t.x = to_tf32(v.x); t.y = to_tf32(v.y); t.z = to_tf32(v.z); t.w = to_tf32(v.w);
            *(float4*)&As[r * 68 + c4 * 4] = t;
        }
        #pragma unroll
        for (int i = 0; i < 4; i++) {
            int idx = tid + i * 256;
            int r = idx >> 4, c4 = idx & 15;
            float4 v = *(const float4*)&B[(size_t)(k0 + r) * N + col0 + c4 * 4];
            float4 t;
            t.x = to_tf32(v.x); t.y = to_tf32(v.y); t.z = to_tf32(v.z); t.w = to_tf32(v.w);
            *(float4*)&Bs[r * 72 + c4 * 4] = t;
        }
        __syncthreads();
        wgemm<8, 8>(acc, As + w * 16 * 68, 68, Bs, 72, g, qt);
        __syncthreads();
    }
    if (MODE == 3 && col0 >= 512) {
        // K/V tile: pack (c, c+32) bf16 pairs to g_kb / g_vb; no fp32 store.
        bool isK = (col0 < 1024);
        uint32_t* dstBase = (uint32_t*)(isK ? g_kb : g_vb);
        int obase = col0 - (isK ? 512 : 1024);
        #pragma unroll
        for (int j = 0; j < 4; j++) {
            int c = col0 + j * 8 + 2 * qt;
            int o = obase + j * 8 + 2 * qt;
            int dp = o >> 6, hh = o & 31;
            float b00 = bias[c],      b01 = bias[c + 1];
            float b10 = bias[c + 32], b11 = bias[c + 33];
            #pragma unroll
            for (int hf = 0; hf < 2; hf++) {
                int r = row0 + w * 16 + g + hf * 8;
                uint32_t* d = dstBase + (size_t)r * 256 + dp * 32 + hh;
                d[0] = packbf(acc[j][hf * 2 + 0] + b00, acc[j + 4][hf * 2 + 0] + b10);
                d[1] = packbf(acc[j][hf * 2 + 1] + b01, acc[j + 4][hf * 2 + 1] + b11);
            }
        }
        return;
    }
    #pragma unroll
    for (int j = 0; j < 8; j++) {
        int col = col0 + j * 8 + 2 * qt;
        #pragma unroll
        for (int hf = 0; hf < 2; hf++) {
            int r = row0 + w * 16 + g + hf * 8;
            float v0 = acc[j][hf * 2 + 0] + bias[col];
            float v1 = acc[j][hf * 2 + 1] + bias[col + 1];
            if (MODE == 1) {
                float2 rv = *(const float2*)&res[(size_t)r * N + col];
                v0 += rv.x; v1 += rv.y;
            }
            if (MODE == 2) {
                v0 = v0 > 0.f ? v0 : __expf(v0) - 1.f;
                v1 = v1 > 0.f ? v1 : __expf(v1) - 1.f;
            }
            float2 ov; ov.x = v0; ov.y = v1;
            *(float2*)&C[(size_t)r * N + col] = ov;
        }
    }
}

// LN of 64 rows x 64 cols: fp32 src (stride sstr) -> bf16x2 dst (dsb2 u32/row).
DEV_INLINE void ln64b(const float* __restrict__ src, int sstr, uint32_t* __restrict__ dst,
                      int dsb2, const float* __restrict__ gam,
                      const float* __restrict__ bet, int tid)
{
    int r = tid >> 2, sub = tid & 3;
    const float* p = src + r * sstr + sub * 16;
    float x[16]; float s = 0.f, s2 = 0.f;
    #pragma unroll
    for (int i = 0; i < 16; i += 4) {
        float4 v = *(const float4*)(p + i);
        x[i] = v.x; x[i+1] = v.y; x[i+2] = v.z; x[i+3] = v.w;
    }
    #pragma unroll
    for (int i = 0; i < 16; i++) { s += x[i]; s2 += x[i] * x[i]; }
    s  += __shfl_xor_sync(0xffffffffu, s, 1);  s  += __shfl_xor_sync(0xffffffffu, s, 2);
    s2 += __shfl_xor_sync(0xffffffffu, s2, 1); s2 += __shfl_xor_sync(0xffffffffu, s2, 2);
    float mean = s * (1.f / 64.f);
    float rstd = rsqrtf(s2 * (1.f / 64.f) - mean * mean + EPSc);
    uint32_t* d = dst + r * dsb2 + sub * 8;
    #pragma unroll
    for (int i = 0; i < 16; i += 2) {
        int c = sub * 16 + i;
        float y0 = (x[i]     - mean) * rstd * gam[c]     + bet[c];
        float y1 = (x[i + 1] - mean) * rstd * gam[c + 1] + bet[c + 1];
        d[i >> 1] = packbf(y0, y1);
    }
}

// Fused: load e tile from global, keep fp32 copy in sX, LN -> bf16x2 sXb.
DEV_INLINE void ln64g(const float* __restrict__ eg, float* __restrict__ sX,
                      uint32_t* __restrict__ sXb,
                      const float* __restrict__ gam, const float* __restrict__ bet, int tid)
{
    int r = tid >> 2, sub = tid & 3;
    const float* p = eg + r * 64 + sub * 16;
    float* q = sX + r * 68 + sub * 16;
    float x[16]; float s = 0.f, s2 = 0.f;
    #pragma unroll
    for (int i = 0; i < 16; i += 4) {
        float4 v = *(const float4*)(p + i);
        *(float4*)(q + i) = v;
        x[i] = v.x; x[i+1] = v.y; x[i+2] = v.z; x[i+3] = v.w;
    }
    #pragma unroll
    for (int i = 0; i < 16; i++) { s += x[i]; s2 += x[i] * x[i]; }
    s  += __shfl_xor_sync(0xffffffffu, s, 1);  s  += __shfl_xor_sync(0xffffffffu, s, 2);
    s2 += __shfl_xor_sync(0xffffffffu, s2, 1); s2 += __shfl_xor_sync(0xffffffffu, s2, 2);
    float mean = s * (1.f / 64.f);
    float rstd = rsqrtf(s2 * (1.f / 64.f) - mean * mean + EPSc);
    uint32_t* d = sXb + r * 36 + sub * 8;
    #pragma unroll
    for (int i = 0; i < 16; i += 2) {
        int c = sub * 16 + i;
        float y0 = (x[i]     - mean) * rstd * gam[c]     + bet[c];
        float y1 = (x[i + 1] - mean) * rstd * gam[c + 1] + bet[c + 1];
        d[i >> 1] = packbf(y0, y1);
    }
}

// ---------------- edge pipeline: 64 rows/CTA, 256 threads, 4 CTA/SM ------------
constexpr int EA_SMEM_BYTES = (4352 + 2304 + 1280 + 4352) * 4;  // 49152

__global__ void __launch_bounds__(256, 4) ea_kernel(
    const float* __restrict__ e, const float* __restrict__ mask,
    const float* __restrict__ lng, const float* __restrict__ lnb,
    const float* __restrict__ flg, const float* __restrict__ flb,
    const float* __restrict__ b_E,  const float* __restrict__ b_G,
    const float* __restrict__ b_Oe, const float* __restrict__ b_e1,
    const float* __restrict__ b_e2,
    float* __restrict__ e_out)
{
    extern __shared__ float sm[];
    float*    sX  = sm;                          // 64 x 68 fp32 (e, then e2)
    uint32_t* sXb = (uint32_t*)(sm + 4352);      // 64 x 36 u32 (eln/eff bf16x2)
    uint32_t* sAb = (uint32_t*)(sm + 6656);      // 64 x 20 u32 (H bf16x2)
    uint32_t* sTb = (uint32_t*)(sm + 7936);      // 64 x 68 u32 (T bf16x2)

    int tid = threadIdx.x;
    int blk = blockIdx.x;
    int bl  = blk >> 2, quad = blk & 3;
    int m0  = quad * 64;
    size_t R0 = (size_t)bl * 256 + m0;

    int w   = tid >> 5;
    int wm2 = w >> 2, wn = w & 3;       // rows wm2*32, col quarter wn
    int g   = (tid & 31) >> 2, qt = tid & 3;
    int rowb = wm2 * 32;

    const uint32_t* WEGu = (const uint32_t*)g_WEGb;
    const uint32_t* WOeu = (const uint32_t*)g_WOeb;
    const uint32_t* We1u = (const uint32_t*)g_We1b;
    const uint32_t* We2u = (const uint32_t*)g_We2b;

    // Pa: load e + LN(e) -> sX (fp32 copy) and sXb (bf16)
    ln64g(e + R0 * 64, sX, sXb, lng, lnb, tid);
    __syncthreads();

    // Pb: GEMM1 (E|G)
    float c1[2][2][4] = {};
    wgemm_b<2, 2, 4, 64>(c1, sXb + rowb * 36, 36, WEGu + wn * 256, g, qt);
    __syncthreads();

    // Pc: epilogue — wn<2: H (A from g_Ab, cols 0..31) -> g_Hb + sAb ;
    //                wn>=2: gate -> g_gateb
    {
        #pragma unroll
        for (int tm = 0; tm < 2; tm++) {
            float mk0 = mask[(size_t)bl * 256 + m0 + rowb + tm * 16 + g];
            float mk1 = mask[(size_t)bl * 256 + m0 + rowb + tm * 16 + g + 8];
            #pragma unroll
            for (int j = 0; j < 2; j++) {
                int colg = wn * 16 + j * 8 + 2 * qt;
                if (wn < 2) {
                    int col = colg;
                    float bv0 = b_E[col], bv1 = b_E[col + 1];
                    #pragma unroll
                    for (int hf = 0; hf < 2; hf++) {
                        int r = rowb + tm * 16 + g + hf * 8;
                        uint32_t aw = ((const uint32_t*)g_Ab)[(R0 + r) * 16 + (col >> 1)];
                        float2 Af = __bfloat1622float2(*(__nv_bfloat162*)&aw);
                        float H0 = fminf(fmaxf(Af.x, -5.f), 5.f) + c1[tm][j][hf * 2 + 0] + bv0;
                        float H1 = fminf(fmaxf(Af.y, -5.f), 5.f) + c1[tm][j][hf * 2 + 1] + bv1;
                        float mk = hf ? mk1 : mk0;
                        g_Hb[(R0 + r) * 16 + (col >> 1)] = packbf(H0 + mk, H1 + mk);
                        sAb[r * 20 + (col >> 1)] = packbf(H0, H1);
                    }
                } else {
                    int col = colg - 32;
                    float bv0 = b_G[col], bv1 = b_G[col + 1];
                    #pragma unroll
                    for (int hf = 0; hf < 2; hf++) {
                        int r = rowb + tm * 16 + g + hf * 8;
                        float mk = hf ? mk1 : mk0;
                        float g0 = 1.f / (1.f + __expf(-(c1[tm][j][hf * 2 + 0] + bv0 + mk)));
                        float g1 = 1.f / (1.f + __expf(-(c1[tm][j][hf * 2 + 1] + bv1 + mk)));
                        g_gateb[(R0 + r) * 16 + (col >> 1)] = packbf(g0, g1);
                    }
                }
            }
        }
    }
    __syncthreads();

    // Pd: GEMM2  e2 = H @ W_Oe + b + e(sX)   (sX overwrite; no reg copy)
    {
        float c2[2][2][4] = {};
        wgemm_b<2, 2, 2, 64>(c2, sAb + rowb * 20, 20, WOeu + wn * 256, g, qt);
        #pragma unroll
        for (int tm = 0; tm < 2; tm++)
            #pragma unroll
            for (int j = 0; j < 2; j++) {
                int col = wn * 16 + j * 8 + 2 * qt;
                float bo0 = b_Oe[col], bo1 = b_Oe[col + 1];
                #pragma unroll
                for (int hf = 0; hf < 2; hf++) {
                    int r = rowb + tm * 16 + g + hf * 8;
                    sX[r * 68 + col]     = c2[tm][j][hf * 2 + 0] + bo0 + sX[r * 68 + col];
                    sX[r * 68 + col + 1] = c2[tm][j][hf * 2 + 1] + bo1 + sX[r * 68 + col + 1];
                }
            }
    }
    __syncthreads();

    // Pe: LN(e2) -> sXb (bf16 eff)
    ln64b(sX, 68, sXb, 36, flg, flb, tid);
    __syncthreads();

    // Pf: GEMM3  T = elu(eff @ W_e1 + b) -> sTb, two 16-col halves per warp
    #pragma unroll
    for (int half = 0; half < 2; half++) {
        float c3[2][2][4] = {};
        int cb = wn * 32 + half * 16;
        wgemm_b<2, 2, 4, 128>(c3, sXb + rowb * 36, 36, We1u + cb * 16, g, qt);
        #pragma unroll
        for (int tm = 0; tm < 2; tm++)
            #pragma unroll
            for (int j = 0; j < 2; j++) {
                int col = cb + j * 8 + 2 * qt;
                float bb0 = b_e1[col], bb1 = b_e1[col + 1];
                #pragma unroll
                for (int hf = 0; hf < 2; hf++) {
                    int r = rowb + tm * 16 + g + hf * 8;
                    float v0 = c3[tm][j][hf * 2 + 0] + bb0;
                    float v1 = c3[tm][j][hf * 2 + 1] + bb1;
                    v0 = v0 > 0.f ? v0 : __expf(v0) - 1.f;
                    v1 = v1 > 0.f ? v1 : __expf(v1) - 1.f;
                    sTb[r * 68 + (col >> 1)] = packbf(v0, v1);
                }
            }
    }
    __syncthreads();

    // Pg: GEMM4  e_out = T @ W_e2 + b + e2(sX)
    {
        float c4[2][2][4] = {};
        wgemm_b<2, 2, 8, 64>(c4, sTb + rowb * 68, 68, We2u + wn * 256, g, qt);
        #pragma unroll
        for (int tm = 0; tm < 2; tm++)
            #pragma unroll
            for (int j = 0; j < 2; j++) {
                int col = wn * 16 + j * 8 + 2 * qt;
                float bz0 = b_e2[col], bz1 = b_e2[col + 1];
                #pragma unroll
                for (int hf = 0; hf < 2; hf++) {
                    int r = rowb + tm * 16 + g + hf * 8;
                    float2 ov;
                    ov.x = c4[tm][j][hf * 2 + 0] + bz0 + sX[r * 68 + col];
                    ov.y = c4[tm][j][hf * 2 + 1] + bz1 + sX[r * 68 + col + 1];
                    *(float2*)&e_out[(R0 + r) * 64 + col] = ov;
                }
            }
    }
}

// ---------------- softmax + gated V accumulation: one block per (b,l) ----------
__global__ void __launch_bounds__(256) eb_kernel()
{
    __shared__ float sH[256 * 36];
    __shared__ float sRed[256];
    __shared__ float sRed2[256];

    int tid = threadIdx.x;
    int bl  = blockIdx.x;
    int b   = bl >> 8;

    const uint4* Hg = (const uint4*)(g_Hb + (size_t)bl * 4096);
    #pragma unroll
    for (int i = 0; i < 4; i++) {
        int idx = tid + i * 256;          // 1024 uint4
        int m = idx >> 2, q = idx & 3;
        uint4 hv = Hg[idx];
        uint32_t ws[4] = {hv.x, hv.y, hv.z, hv.w};
        #pragma unroll
        for (int j = 0; j < 4; j++) {
            float2 f = __bfloat1622float2(*(__nv_bfloat162*)&ws[j]);
            sH[m * 36 + q * 8 + 2 * j]     = f.x;
            sH[m * 36 + q * 8 + 2 * j + 1] = f.y;
        }
    }
    __syncthreads();

    int h = tid & 31, grp = tid >> 5;
    float pmax = -1e30f;
    for (int mm = 0; mm < 32; mm++) {
        int m = grp * 32 + mm;
        pmax = fmaxf(pmax, sH[m * 36 + h]);
    }
    sRed[grp * 32 + h] = pmax;
    __syncthreads();
    float M = -1e30f;
    #pragma unroll
    for (int gg = 0; gg < 8; gg++) M = fmaxf(M, sRed[gg * 32 + h]);

    const uint32_t* gateR = g_gateb + (size_t)bl * 4096;
    float ssum = 0.f;
    for (int mm = 0; mm < 32; mm++) {
        int m = grp * 32 + mm;
        float wv = __expf(sH[m * 36 + h] - M);
        ssum += wv;
        uint32_t gw = gateR[m * 16 + (h >> 1)];
        float2 gf = __bfloat1622float2(*(__nv_bfloat162*)&gw);
        float gate = (h & 1) ? gf.y : gf.x;
        sH[m * 36 + h] = wv * gate;
    }
    sRed2[grp * 32 + h] = ssum;
    __syncthreads();
    float S = 0.f;
    #pragma unroll
    for (int gg = 0; gg < 8; gg++) S += sRed2[gg * 32 + h];
    float inv = 1.f / S;

    float a0 = 0.f, a1 = 0.f;
    const __nv_bfloat162* Vb = g_vb + (size_t)(b * 256) * 256 + grp * 32 + h;
    #pragma unroll 8
    for (int m = 0; m < 256; m++) {
        float wv = sH[m * 36 + h];
        float2 vv = __bfloat1622float2(Vb[(size_t)m * 256]);
        a0 += wv * vv.x;
        a1 += wv * vv.y;
    }
    int k0 = grp * 2;
    g_vatt[(size_t)bl * 512 + k0 * 32 + h]       = a0 * inv;
    g_vatt[(size_t)bl * 512 + (k0 + 1) * 32 + h] = a1 * inv;
}

// ---------------- launch ----------------
extern "C" void kernel_launch(void* const* d_in, const int* in_sizes, int n_in,
                              void* d_out, int out_size)
{
    const float* h         = (const float*)d_in[0];
    const float* e         = (const float*)d_in[1];
    const float* mask      = (const float*)d_in[2];
    const float* ln_h_g    = (const float*)d_in[3];
    const float* ln_h_b    = (const float*)d_in[4];
    const float* ln_e_g    = (const float*)d_in[5];
    const float* ln_e_b    = (const float*)d_in[6];
    const float* ffn_ln_h_g= (const float*)d_in[7];
    const float* ffn_ln_h_b= (const float*)d_in[8];
    const float* ffn_ln_e_g= (const float*)d_in[9];
    const float* ffn_ln_e_b= (const float*)d_in[10];
    const float* W_qkv     = (const float*)d_in[11];
    const float* b_qkv     = (const float*)d_in[12];
    const float* W_E       = (const float*)d_in[13];
    const float* b_E       = (const float*)d_in[14];
    const float* W_G       = (const float*)d_in[15];
    const float* b_G       = (const float*)d_in[16];
    const float* W_Oh      = (const float*)d_in[17];
    const float* b_Oh      = (const float*)d_in[18];
    const float* W_h1      = (const float*)d_in[19];
    const float* b_h1      = (const float*)d_in[20];
    const float* W_h2      = (const float*)d_in[21];
    const float* b_h2      = (const float*)d_in[22];
    const float* W_Oe      = (const float*)d_in[23];
    const float* b_Oe      = (const float*)d_in[24];
    const float* W_e1      = (const float*)d_in[25];
    const float* b_e1      = (const float*)d_in[26];
    const float* W_e2      = (const float*)d_in[27];
    const float* b_e2      = (const float*)d_in[28];

    float* h_out = (float*)d_out;
    float* e_out = (float*)d_out + (size_t)ROWS * DNn;

    float *p_hln, *p_qkv, *p_vatt, *p_h2, *p_hff, *p_t;
    cudaGetSymbolAddress((void**)&p_hln,  g_hln);
    cudaGetSymbolAddress((void**)&p_qkv,  g_qkv);
    cudaGetSymbolAddress((void**)&p_vatt, g_vatt);
    cudaGetSymbolAddress((void**)&p_h2,   g_h2);
    cudaGetSymbolAddress((void**)&p_hff,  g_hff);
    cudaGetSymbolAddress((void**)&p_t,    g_t);

    cudaFuncSetAttribute(ea_kernel, cudaFuncAttributeMaxDynamicSharedMemorySize,
                         EA_SMEM_BYTES);
    cudaFuncSetAttribute(qk_kernel, cudaFuncAttributeMaxDynamicSharedMemorySize,
                         QK_SMEM_BYTES);
    cudaFuncSetAttribute(tgemm_tf<1>, cudaFuncAttributeMaxDynamicSharedMemorySize,
                         TG_SMEM_BYTES);
    cudaFuncSetAttribute(tgemm_tf<2>, cudaFuncAttributeMaxDynamicSharedMemorySize,
                         TG_SMEM_BYTES);
    cudaFuncSetAttribute(tgemm_tf<3>, cudaFuncAttributeMaxDynamicSharedMemorySize,
                         TG_SMEM_BYTES);

    // 0) pack edge weights (bf16 fragments)
    pack_weights<<<88, 256>>>(W_E, W_G, W_Oe, W_e1, W_e2);
    // 1) h_ln
    ln512_kernel<<<ROWS, 128>>>(h, ln_h_g, ln_h_b, p_hln);
    // 2) QKV (tf32); Q -> g_qkv fp32, K/V -> g_kb/g_vb bf16 (fused pack)
    tgemm_tf<3><<<dim3(1536/64, ROWS/128), 256, TG_SMEM_BYTES>>>(p_hln, W_qkv, p_qkv,
                                                  b_qkv, nullptr, ROWS, 1536, 512);
    // 2.6) QK precompute: A_hat (K unpack amortized over 4 l's per thread)
    qk_kernel<<<Bn * 4 * 8, 256, QK_SMEM_BYTES>>>();
    // 3) edge pipeline (writes e_out, g_Hb(+mask), g_gateb)
    ea_kernel<<<ROWS * 4, 256, EA_SMEM_BYTES>>>(e, mask, ln_e_g, ln_e_b,
        ffn_ln_e_g, ffn_ln_e_b, b_E, b_G, b_Oe, b_e1, b_e2, e_out);
    // 4) softmax + gated V accumulation (writes g_vatt)
    eb_kernel<<<ROWS, 256>>>();
    // 5) h2 = V_att @ W_Oh + b + h
    tgemm_tf<1><<<dim3(512/64, ROWS/128), 256, TG_SMEM_BYTES>>>(p_vatt, W_Oh, p_h2,
                                                 b_Oh, h, ROWS, 512, 512);
    // 6) h_ff = LN(h2)
    ln512_kernel<<<ROWS, 128>>>(p_h2, ffn_ln_h_g, ffn_ln_h_b, p_hff);
    // 7) t = elu(h_ff @ W_h1 + b)
    tgemm_tf<2><<<dim3(1024/64, ROWS/128), 256, TG_SMEM_BYTES>>>(p_hff, W_h1, p_t,
                                                  b_h1, nullptr, ROWS, 1024, 512);
    // 8) h_out = t @ W_h2 + b + h2
    tgemm_tf<1><<<dim3(512/64, ROWS/128), 256, TG_SMEM_BYTES>>>(p_t, W_h2, h_out,
                                                 b_h2, p_h2, ROWS, 512, 1024);
}

// round 15
// speedup vs baseline: 1.2141x; 1.0527x over previous
#include <cuda_runtime.h>
#include <cuda_bf16.h>
#include <math.h>
#include <stdint.h>

#define DEV_INLINE __device__ __forceinline__

constexpr int Bn = 32, Ln = 256, DNn = 512;
constexpr int ROWS = Bn * Ln;            // 8192 (b,l) rows
constexpr int EROWS = ROWS * Ln;         // 2,097,152 edge rows
constexpr int FNn = 1024;
constexpr float EPSc = 1e-5f;

// ---------------- device scratch ----------------
__device__ float g_hln[ROWS * DNn];
__device__ float g_qkv[ROWS * 3 * DNn];       // only Q region (cols 0..511) written
__device__ float g_vatt[ROWS * DNn];
__device__ float g_h2[ROWS * DNn];
__device__ float g_hff[ROWS * DNn];
__device__ float g_t[ROWS * FNn];
__device__ uint32_t g_Hb[(size_t)EROWS * 16];     // H_hat + mask, bf16x2
__device__ uint32_t g_gateb[(size_t)EROWS * 16];  // sigmoid(G+mask), bf16x2
__device__ __nv_bfloat16 g_Ab[(size_t)EROWS * 32];// A_hat (scaled), bf16
__device__ uint32_t g_Wt[(size_t)ROWS * 4096];    // softmax weights, bf16 m-pairs
// bf16 fragment-packed edge weights (see packB); bf16 K and V
__device__ __nv_bfloat16 g_WEGb[64 * 64];
__device__ __nv_bfloat16 g_WOeb[32 * 64];
__device__ __nv_bfloat16 g_We1b[64 * 128];
__device__ __nv_bfloat16 g_We2b[128 * 64];
__device__ __nv_bfloat162 g_kb[(size_t)ROWS * 256];   // [(row)*256 + dp*32 + h]
__device__ __nv_bfloat162 g_vb[(size_t)ROWS * 256];   // [(row)*256 + kp*32 + h]

DEV_INLINE uint32_t packbf(float a, float b) {
    __nv_bfloat162 h2 = __floats2bfloat162_rn(a, b);
    return *(uint32_t*)&h2;
}

DEV_INLINE float to_tf32(float x) {
    float y;
    asm("cvt.rna.tf32.f32 %0, %1;" : "=f"(y) : "f"(x));
    return y;
}

DEV_INLINE void mma8(float c[4], uint32_t a0, uint32_t a1, uint32_t a2, uint32_t a3,
                     uint32_t b0, uint32_t b1)
{
    asm volatile(
        "mma.sync.aligned.m16n8k8.row.col.f32.tf32.tf32.f32 "
        "{%0,%1,%2,%3},{%4,%5,%6,%7},{%8,%9},{%0,%1,%2,%3};"
        : "+f"(c[0]), "+f"(c[1]), "+f"(c[2]), "+f"(c[3])
        : "r"(a0), "r"(a1), "r"(a2), "r"(a3), "r"(b0), "r"(b1));
}

DEV_INLINE void mma16(float c[4], uint32_t a0, uint32_t a1, uint32_t a2, uint32_t a3,
                      uint32_t b0, uint32_t b1)
{
    asm volatile(
        "mma.sync.aligned.m16n8k16.row.col.f32.bf16.bf16.f32 "
        "{%0,%1,%2,%3},{%4,%5,%6,%7},{%8,%9},{%0,%1,%2,%3};"
        : "+f"(c[0]), "+f"(c[1]), "+f"(c[2]), "+f"(c[3])
        : "r"(a0), "r"(a1), "r"(a2), "r"(a3), "r"(b0), "r"(b1));
}

// smem-B tf32 warp GEMM (h-path)
template<int NTW, int KS>
DEV_INLINE void wgemm(float c[NTW][4], const float* __restrict__ Arow, int lda,
                      const float* __restrict__ Bcol, int ldb, int g, int qt)
{
    #pragma unroll
    for (int ks = 0; ks < KS; ks++) {
        int k = ks * 8;
        uint32_t a0 = __float_as_uint(Arow[(g)     * lda + k + qt]);
        uint32_t a1 = __float_as_uint(Arow[(g + 8) * lda + k + qt]);
        uint32_t a2 = __float_as_uint(Arow[(g)     * lda + k + qt + 4]);
        uint32_t a3 = __float_as_uint(Arow[(g + 8) * lda + k + qt + 4]);
        #pragma unroll
        for (int j = 0; j < NTW; j++) {
            uint32_t b0 = __float_as_uint(Bcol[(k + qt)     * ldb + j * 8 + g]);
            uint32_t b1 = __float_as_uint(Bcol[(k + qt + 4) * ldb + j * 8 + g]);
            mma8(c[j], a0, a1, a2, a3, b0, b1);
        }
    }
}

// bf16 warp GEMM, m16n8k16. A in smem as u32 (bf16x2), sb2 = u32 words per row.
template<int TM, int NTW, int S, int N>
DEV_INLINE void wgemm_b(float c[TM][NTW][4], const uint32_t* __restrict__ As, int sb2,
                        const uint32_t* __restrict__ Bp, int g, int qt)
{
    #pragma unroll
    for (int t = 0; t < (S + 1) / 2; t++) {
        uint4 bq[NTW];
        #pragma unroll
        for (int j = 0; j < NTW; j++)
            bq[j] = *(const uint4*)&Bp[(t * (N * 4) + (j * 8 + g) * 4 + qt) * 4];
        #pragma unroll
        for (int se = 0; se < 2; se++) {
            int s = 2 * t + se;
            if (s >= S) break;
            #pragma unroll
            for (int tm = 0; tm < TM; tm++) {
                const uint32_t* Ar = As + tm * 16 * sb2;
                uint32_t a0 = Ar[(g)     * sb2 + 8 * s + qt];
                uint32_t a2 = Ar[(g)     * sb2 + 8 * s + qt + 4];
                uint32_t a1 = Ar[(g + 8) * sb2 + 8 * s + qt];
                uint32_t a3 = Ar[(g + 8) * sb2 + 8 * s + qt + 4];
                #pragma unroll
                for (int j = 0; j < NTW; j++) {
                    uint32_t b0 = se ? bq[j].z : bq[j].x;
                    uint32_t b1 = se ? bq[j].w : bq[j].y;
                    mma16(c[tm][j], a0, a1, a2, a3, b0, b1);
                }
            }
        }
    }
}

// bf16 fragment pack index: element (k,n) of a KxN col-fragment weight.
DEV_INLINE int packB(int n, int k, int N) {
    int p = k >> 1, lo = k & 1;
    int qt = p & 3, half = (p >> 2) & 1, s = p >> 3;
    int t = s >> 1, se = s & 1;
    int u32i = (t * (N * 4) + n * 4 + qt) * 4 + se * 2 + half;
    return u32i * 2 + lo;
}

__global__ void pack_weights(const float* __restrict__ W_E, const float* __restrict__ W_G,
                             const float* __restrict__ W_Oe, const float* __restrict__ W_e1,
                             const float* __restrict__ W_e2)
{
    int i = blockIdx.x * 256 + threadIdx.x;
    if (i < 4096) {                       // WEG: K=64, N=64
        int k = i >> 6, n = i & 63;
        float v = n < 32 ? W_E[k * 32 + n] : W_G[k * 32 + n - 32];
        g_WEGb[packB(n, k, 64)] = __float2bfloat16(v);
    } else if (i < 6144) {                // WOe: K=32, N=64
        int j = i - 4096; int k = j >> 6, n = j & 63;
        g_WOeb[packB(n, k, 64)] = __float2bfloat16(W_Oe[j]);
    } else if (i < 14336) {               // We1: K=64, N=128
        int j = i - 6144; int k = j >> 7, n = j & 127;
        g_We1b[packB(n, k, 128)] = __float2bfloat16(W_e1[j]);
    } else if (i < 22528) {               // We2: K=128, N=64
        int j = i - 14336; int k = j >> 6, n = j & 63;
        g_We2b[packB(n, k, 64)] = __float2bfloat16(W_e2[j]);
    }
}

// ---------------- QK precompute: A_hat, 4 l's per thread --------------------
constexpr int QK_SMEM_BYTES = 64 * 256 * 4;   // 65536

__global__ void __launch_bounds__(256, 2) qk_kernel()
{
    extern __shared__ uint32_t ks[];   // [64][256] bf16x2 words
    int blk = blockIdx.x;
    int lt = blk & 7, mt = (blk >> 3) & 3, b = blk >> 5;
    int m0 = mt * 64, l0 = lt * 32;
    int tid = threadIdx.x;

    const uint4* Ksrc = (const uint4*)(g_kb + ((size_t)(b * 256) + m0) * 256);
    uint4* Kdst = (uint4*)ks;
    #pragma unroll
    for (int i = 0; i < 16; i++)
        Kdst[tid + i * 256] = Ksrc[tid + i * 256];
    __syncthreads();

    int h = tid & 31, lg = tid >> 5;
    int l = l0 + lg * 4;
    int bl = b * 256 + l;

    float q[4][16];
    #pragma unroll
    for (int li = 0; li < 4; li++) {
        const float* Qp = g_qkv + (size_t)(bl + li) * 1536 + h;
        #pragma unroll
        for (int d = 0; d < 16; d++) q[li][d] = Qp[d * 32];
    }

    __nv_bfloat16* Ad0 = g_Ab + ((size_t)(bl + 0) * 256 + m0) * 32 + h;
    __nv_bfloat16* Ad1 = g_Ab + ((size_t)(bl + 1) * 256 + m0) * 32 + h;
    __nv_bfloat16* Ad2 = g_Ab + ((size_t)(bl + 2) * 256 + m0) * 32 + h;
    __nv_bfloat16* Ad3 = g_Ab + ((size_t)(bl + 3) * 256 + m0) * 32 + h;

    #pragma unroll 2
    for (int m = 0; m < 64; m++) {
        const uint32_t* Kp = ks + m * 256 + h;
        float kf[16];
        #pragma unroll
        for (int dp = 0; dp < 8; dp++) {
            uint32_t wv = Kp[dp * 32];
            kf[2 * dp]     = __uint_as_float(wv << 16);
            kf[2 * dp + 1] = __uint_as_float(wv & 0xffff0000u);
        }
        float a0 = 0.f, a1 = 0.f, a2 = 0.f, a3 = 0.f;
        #pragma unroll
        for (int d = 0; d < 16; d++) {
            a0 += q[0][d] * kf[d];
            a1 += q[1][d] * kf[d];
            a2 += q[2][d] * kf[d];
            a3 += q[3][d] * kf[d];
        }
        Ad0[(size_t)m * 32] = __float2bfloat16(a0 * 0.25f);
        Ad1[(size_t)m * 32] = __float2bfloat16(a1 * 0.25f);
        Ad2[(size_t)m * 32] = __float2bfloat16(a2 * 0.25f);
        Ad3[(size_t)m * 32] = __float2bfloat16(a3 * 0.25f);
    }
}

// ---------------- LayerNorm over 512, one block per row ----------------
__global__ void __launch_bounds__(128) ln512_kernel(
    const float* __restrict__ x, const float* __restrict__ g,
    const float* __restrict__ b, float* __restrict__ y)
{
    int row = blockIdx.x, tid = threadIdx.x;
    const float4* xr = (const float4*)(x + (size_t)row * 512);
    float4 v = xr[tid];
    float s  = v.x + v.y + v.z + v.w;
    float s2 = v.x*v.x + v.y*v.y + v.z*v.z + v.w*v.w;
    #pragma unroll
    for (int o = 16; o; o >>= 1) {
        s  += __shfl_xor_sync(0xffffffffu, s,  o);
        s2 += __shfl_xor_sync(0xffffffffu, s2, o);
    }
    __shared__ float aS[4], aS2[4];
    if ((tid & 31) == 0) { aS[tid >> 5] = s; aS2[tid >> 5] = s2; }
    __syncthreads();
    s  = aS[0] + aS[1] + aS[2] + aS[3];
    s2 = aS2[0] + aS2[1] + aS2[2] + aS2[3];
    float mean = s * (1.f / 512.f);
    float rstd = rsqrtf(s2 * (1.f / 512.f) - mean * mean + EPSc);
    int c = tid * 4;
    float4 gv = *(const float4*)(g + c);
    float4 bv = *(const float4*)(b + c);
    float4 o;
    o.x = (v.x - mean) * rstd * gv.x + bv.x;
    o.y = (v.y - mean) * rstd * gv.y + bv.y;
    o.z = (v.z - mean) * rstd * gv.z + bv.z;
    o.w = (v.w - mean) * rstd * gv.w + bv.w;
    ((float4*)(y + (size_t)row * 512))[tid] = o;
}

// ---------------- tf32 tensor GEMM (h-path; MODE 3 = QKV with K/V bf16 pack) --
constexpr int TG_SMEM_BYTES = (128 * 68 + 64 * 72) * 4;   // 53248
template<int MODE>
__global__ void __launch_bounds__(256) tgemm_tf(
    const float* __restrict__ A, const float* __restrict__ B, float* __restrict__ C,
    const float* __restrict__ bias, const float* __restrict__ res,
    int M, int N, int K)
{
    extern __shared__ float ts[];
    float* As = ts;              // 128 x 68
    float* Bs = ts + 128 * 68;   // 64 x 72
    int tid = threadIdx.x;
    int row0 = blockIdx.y * 128, col0 = blockIdx.x * 64;
    int w = tid >> 5;
    int g = (tid & 31) >> 2, qt = tid & 3;
    float acc[8][4] = {};

    for (int k0 = 0; k0 < K; k0 += 64) {
        #pragma unroll
        for (int i = 0; i < 8; i++) {
            int idx = tid + i * 256;
            int r = idx >> 4, c4 = idx & 15;
            float4 v = *(const float4*)&A[(size_t)(row0 + r) * K + k0 + c4 * 4];
            float4 t;
            t.x = to_tf32(v.x); t.y = to_tf32(v.y); t.z = to_tf32(v.z); t.w = to_tf32(v.w);
            *(float4*)&As[r * 68 + c4 * 4] = t;
        }
        #pragma unroll
        for (int i = 0; i < 4; i++) {
            int idx = tid + i * 256;
            int r = idx >> 4, c4 = idx & 15;
            float4 v = *(const float4*)&B[(size_t)(k0 + r) * N + col0 + c4 * 4];
            float4 t;
            t.x = to_tf32(v.x); t.y = to_tf32(v.y); t.z = to_tf32(v.z); t.w = to_tf32(v.w);
            *(float4*)&Bs[r * 72 + c4 * 4] = t;
        }
        __syncthreads();
        wgemm<8, 8>(acc, As + w * 16 * 68, 68, Bs, 72, g, qt);
        __syncthreads();
    }
    if (MODE == 3 && col0 >= 512) {
        bool isK = (col0 < 1024);
        uint32_t* dstBase = (uint32_t*)(isK ? g_kb : g_vb);
        int obase = col0 - (isK ? 512 : 1024);
        #pragma unroll
        for (int j = 0; j < 4; j++) {
            int c = col0 + j * 8 + 2 * qt;
            int o = obase + j * 8 + 2 * qt;
            int dp = o >> 6, hh = o & 31;
            float b00 = bias[c],      b01 = bias[c + 1];
            float b10 = bias[c + 32], b11 = bias[c + 33];
            #pragma unroll
            for (int hf = 0; hf < 2; hf++) {
                int r = row0 + w * 16 + g + hf * 8;
                uint32_t* d = dstBase + (size_t)r * 256 + dp * 32 + hh;
                d[0] = packbf(acc[j][hf * 2 + 0] + b00, acc[j + 4][hf * 2 + 0] + b10);
                d[1] = packbf(acc[j][hf * 2 + 1] + b01, acc[j + 4][hf * 2 + 1] + b11);
            }
        }
        return;
    }
    #pragma unroll
    for (int j = 0; j < 8; j++) {
        int col = col0 + j * 8 + 2 * qt;
        #pragma unroll
        for (int hf = 0; hf < 2; hf++) {
            int r = row0 + w * 16 + g + hf * 8;
            float v0 = acc[j][hf * 2 + 0] + bias[col];
            float v1 = acc[j][hf * 2 + 1] + bias[col + 1];
            if (MODE == 1) {
                float2 rv = *(const float2*)&res[(size_t)r * N + col];
                v0 += rv.x; v1 += rv.y;
            }
            if (MODE == 2) {
                v0 = v0 > 0.f ? v0 : __expf(v0) - 1.f;
                v1 = v1 > 0.f ? v1 : __expf(v1) - 1.f;
            }
            float2 ov; ov.x = v0; ov.y = v1;
            *(float2*)&C[(size_t)r * N + col] = ov;
        }
    }
}

// LN of 64 rows x 64 cols: fp32 src (stride sstr) -> bf16x2 dst (dsb2 u32/row).
DEV_INLINE void ln64b(const float* __restrict__ src, int sstr, uint32_t* __restrict__ dst,
                      int dsb2, const float* __restrict__ gam,
                      const float* __restrict__ bet, int tid)
{
    int r = tid >> 2, sub = tid & 3;
    const float* p = src + r * sstr + sub * 16;
    float x[16]; float s = 0.f, s2 = 0.f;
    #pragma unroll
    for (int i = 0; i < 16; i += 4) {
        float4 v = *(const float4*)(p + i);
        x[i] = v.x; x[i+1] = v.y; x[i+2] = v.z; x[i+3] = v.w;
    }
    #pragma unroll
    for (int i = 0; i < 16; i++) { s += x[i]; s2 += x[i] * x[i]; }
    s  += __shfl_xor_sync(0xffffffffu, s, 1);  s  += __shfl_xor_sync(0xffffffffu, s, 2);
    s2 += __shfl_xor_sync(0xffffffffu, s2, 1); s2 += __shfl_xor_sync(0xffffffffu, s2, 2);
    float mean = s * (1.f / 64.f);
    float rstd = rsqrtf(s2 * (1.f / 64.f) - mean * mean + EPSc);
    uint32_t* d = dst + r * dsb2 + sub * 8;
    #pragma unroll
    for (int i = 0; i < 16; i += 2) {
        int c = sub * 16 + i;
        float y0 = (x[i]     - mean) * rstd * gam[c]     + bet[c];
        float y1 = (x[i + 1] - mean) * rstd * gam[c + 1] + bet[c + 1];
        d[i >> 1] = packbf(y0, y1);
    }
}

// Fused: load e tile from global, keep fp32 copy in sX, LN -> bf16x2 sXb.
DEV_INLINE void ln64g(const float* __restrict__ eg, float* __restrict__ sX,
                      uint32_t* __restrict__ sXb,
                      const float* __restrict__ gam, const float* __restrict__ bet, int tid)
{
    int r = tid >> 2, sub = tid & 3;
    const float* p = eg + r * 64 + sub * 16;
    float* q = sX + r * 68 + sub * 16;
    float x[16]; float s = 0.f, s2 = 0.f;
    #pragma unroll
    for (int i = 0; i < 16; i += 4) {
        float4 v = *(const float4*)(p + i);
        *(float4*)(q + i) = v;
        x[i] = v.x; x[i+1] = v.y; x[i+2] = v.z; x[i+3] = v.w;
    }
    #pragma unroll
    for (int i = 0; i < 16; i++) { s += x[i]; s2 += x[i] * x[i]; }
    s  += __shfl_xor_sync(0xffffffffu, s, 1);  s  += __shfl_xor_sync(0xffffffffu, s, 2);
    s2 += __shfl_xor_sync(0xffffffffu, s2, 1); s2 += __shfl_xor_sync(0xffffffffu, s2, 2);
    float mean = s * (1.f / 64.f);
    float rstd = rsqrtf(s2 * (1.f / 64.f) - mean * mean + EPSc);
    uint32_t* d = sXb + r * 36 + sub * 8;
    #pragma unroll
    for (int i = 0; i < 16; i += 2) {
        int c = sub * 16 + i;
        float y0 = (x[i]     - mean) * rstd * gam[c]     + bet[c];
        float y1 = (x[i + 1] - mean) * rstd * gam[c + 1] + bet[c + 1];
        d[i >> 1] = packbf(y0, y1);
    }
}

// ---------------- edge pipeline: 64 rows/CTA, 256 threads, 4 CTA/SM ------------
constexpr int EA_SMEM_BYTES = (4352 + 2304 + 1280 + 4352) * 4;  // 49152

__global__ void __launch_bounds__(256, 4) ea_kernel(
    const float* __restrict__ e, const float* __restrict__ mask,
    const float* __restrict__ lng, const float* __restrict__ lnb,
    const float* __restrict__ flg, const float* __restrict__ flb,
    const float* __restrict__ b_E,  const float* __restrict__ b_G,
    const float* __restrict__ b_Oe, const float* __restrict__ b_e1,
    const float* __restrict__ b_e2,
    float* __restrict__ e_out)
{
    extern __shared__ float sm[];
    float*    sX  = sm;                          // 64 x 68 fp32 (e, then e2)
    uint32_t* sXb = (uint32_t*)(sm + 4352);      // 64 x 36 u32 (eln/eff bf16x2)
    uint32_t* sAb = (uint32_t*)(sm + 6656);      // 64 x 20 u32 (H bf16x2)
    uint32_t* sTb = (uint32_t*)(sm + 7936);      // 64 x 68 u32 (T bf16x2)

    int tid = threadIdx.x;
    int blk = blockIdx.x;
    int bl  = blk >> 2, quad = blk & 3;
    int m0  = quad * 64;
    size_t R0 = (size_t)bl * 256 + m0;

    int w   = tid >> 5;
    int wm2 = w >> 2, wn = w & 3;
    int g   = (tid & 31) >> 2, qt = tid & 3;
    int rowb = wm2 * 32;

    const uint32_t* WEGu = (const uint32_t*)g_WEGb;
    const uint32_t* WOeu = (const uint32_t*)g_WOeb;
    const uint32_t* We1u = (const uint32_t*)g_We1b;
    const uint32_t* We2u = (const uint32_t*)g_We2b;

    ln64g(e + R0 * 64, sX, sXb, lng, lnb, tid);
    __syncthreads();

    float c1[2][2][4] = {};
    wgemm_b<2, 2, 4, 64>(c1, sXb + rowb * 36, 36, WEGu + wn * 256, g, qt);
    __syncthreads();

    {
        #pragma unroll
        for (int tm = 0; tm < 2; tm++) {
            float mk0 = mask[(size_t)bl * 256 + m0 + rowb + tm * 16 + g];
            float mk1 = mask[(size_t)bl * 256 + m0 + rowb + tm * 16 + g + 8];
            #pragma unroll
            for (int j = 0; j < 2; j++) {
                int colg = wn * 16 + j * 8 + 2 * qt;
                if (wn < 2) {
                    int col = colg;
                    float bv0 = b_E[col], bv1 = b_E[col + 1];
                    #pragma unroll
                    for (int hf = 0; hf < 2; hf++) {
                        int r = rowb + tm * 16 + g + hf * 8;
                        uint32_t aw = ((const uint32_t*)g_Ab)[(R0 + r) * 16 + (col >> 1)];
                        float2 Af = __bfloat1622float2(*(__nv_bfloat162*)&aw);
                        float H0 = fminf(fmaxf(Af.x, -5.f), 5.f) + c1[tm][j][hf * 2 + 0] + bv0;
                        float H1 = fminf(fmaxf(Af.y, -5.f), 5.f) + c1[tm][j][hf * 2 + 1] + bv1;
                        float mk = hf ? mk1 : mk0;
                        g_Hb[(R0 + r) * 16 + (col >> 1)] = packbf(H0 + mk, H1 + mk);
                        sAb[r * 20 + (col >> 1)] = packbf(H0, H1);
                    }
                } else {
                    int col = colg - 32;
                    float bv0 = b_G[col], bv1 = b_G[col + 1];
                    #pragma unroll
                    for (int hf = 0; hf < 2; hf++) {
                        int r = rowb + tm * 16 + g + hf * 8;
                        float mk = hf ? mk1 : mk0;
                        float g0 = 1.f / (1.f + __expf(-(c1[tm][j][hf * 2 + 0] + bv0 + mk)));
                        float g1 = 1.f / (1.f + __expf(-(c1[tm][j][hf * 2 + 1] + bv1 + mk)));
                        g_gateb[(R0 + r) * 16 + (col >> 1)] = packbf(g0, g1);
                    }
                }
            }
        }
    }
    __syncthreads();

    {
        float c2[2][2][4] = {};
        wgemm_b<2, 2, 2, 64>(c2, sAb + rowb * 20, 20, WOeu + wn * 256, g, qt);
        #pragma unroll
        for (int tm = 0; tm < 2; tm++)
            #pragma unroll
            for (int j = 0; j < 2; j++) {
                int col = wn * 16 + j * 8 + 2 * qt;
                float bo0 = b_Oe[col], bo1 = b_Oe[col + 1];
                #pragma unroll
                for (int hf = 0; hf < 2; hf++) {
                    int r = rowb + tm * 16 + g + hf * 8;
                    sX[r * 68 + col]     = c2[tm][j][hf * 2 + 0] + bo0 + sX[r * 68 + col];
                    sX[r * 68 + col + 1] = c2[tm][j][hf * 2 + 1] + bo1 + sX[r * 68 + col + 1];
                }
            }
    }
    __syncthreads();

    ln64b(sX, 68, sXb, 36, flg, flb, tid);
    __syncthreads();

    #pragma unroll
    for (int half = 0; half < 2; half++) {
        float c3[2][2][4] = {};
        int cb = wn * 32 + half * 16;
        wgemm_b<2, 2, 4, 128>(c3, sXb + rowb * 36, 36, We1u + cb * 16, g, qt);
        #pragma unroll
        for (int tm = 0; tm < 2; tm++)
            #pragma unroll
            for (int j = 0; j < 2; j++) {
                int col = cb + j * 8 + 2 * qt;
                float bb0 = b_e1[col], bb1 = b_e1[col + 1];
                #pragma unroll
                for (int hf = 0; hf < 2; hf++) {
                    int r = rowb + tm * 16 + g + hf * 8;
                    float v0 = c3[tm][j][hf * 2 + 0] + bb0;
                    float v1 = c3[tm][j][hf * 2 + 1] + bb1;
                    v0 = v0 > 0.f ? v0 : __expf(v0) - 1.f;
                    v1 = v1 > 0.f ? v1 : __expf(v1) - 1.f;
                    sTb[r * 68 + (col >> 1)] = packbf(v0, v1);
                }
            }
    }
    __syncthreads();

    {
        float c4[2][2][4] = {};
        wgemm_b<2, 2, 8, 64>(c4, sTb + rowb * 68, 68, We2u + wn * 256, g, qt);
        #pragma unroll
        for (int tm = 0; tm < 2; tm++)
            #pragma unroll
            for (int j = 0; j < 2; j++) {
                int col = wn * 16 + j * 8 + 2 * qt;
                float bz0 = b_e2[col], bz1 = b_e2[col + 1];
                #pragma unroll
                for (int hf = 0; hf < 2; hf++) {
                    int r = rowb + tm * 16 + g + hf * 8;
                    float2 ov;
                    ov.x = c4[tm][j][hf * 2 + 0] + bz0 + sX[r * 68 + col];
                    ov.y = c4[tm][j][hf * 2 + 1] + bz1 + sX[r * 68 + col + 1];
                    *(float2*)&e_out[(R0 + r) * 64 + col] = ov;
                }
            }
    }
}

// ---- eb1: softmax + gate; store normalized bf16 weights to g_Wt --------------
__global__ void __launch_bounds__(256) eb1_kernel()
{
    __shared__ float sH[256 * 36];
    __shared__ float sRed[256];
    __shared__ float sRed2[256];
    __shared__ float sInv[32];

    int tid = threadIdx.x;
    int bl  = blockIdx.x;
    int b   = bl >> 8;
    int l   = bl & 255;

    const uint4* Hg = (const uint4*)(g_Hb + (size_t)bl * 4096);
    #pragma unroll
    for (int i = 0; i < 4; i++) {
        int idx = tid + i * 256;
        int m = idx >> 2, q = idx & 3;
        uint4 hv = Hg[idx];
        uint32_t ws[4] = {hv.x, hv.y, hv.z, hv.w};
        #pragma unroll
        for (int j = 0; j < 4; j++) {
            float2 f = __bfloat1622float2(*(__nv_bfloat162*)&ws[j]);
            sH[m * 36 + q * 8 + 2 * j]     = f.x;
            sH[m * 36 + q * 8 + 2 * j + 1] = f.y;
        }
    }
    __syncthreads();

    int h = tid & 31, grp = tid >> 5;
    float pmax = -1e30f;
    for (int mm = 0; mm < 32; mm++) {
        int m = grp * 32 + mm;
        pmax = fmaxf(pmax, sH[m * 36 + h]);
    }
    sRed[grp * 32 + h] = pmax;
    __syncthreads();
    float M = -1e30f;
    #pragma unroll
    for (int gg = 0; gg < 8; gg++) M = fmaxf(M, sRed[gg * 32 + h]);

    const uint32_t* gateR = g_gateb + (size_t)bl * 4096;
    float ssum = 0.f;
    for (int mm = 0; mm < 32; mm++) {
        int m = grp * 32 + mm;
        float wv = __expf(sH[m * 36 + h] - M);
        ssum += wv;
        uint32_t gw = gateR[m * 16 + (h >> 1)];
        float2 gf = __bfloat1622float2(*(__nv_bfloat162*)&gw);
        float gate = (h & 1) ? gf.y : gf.x;
        sH[m * 36 + h] = wv * gate;
    }
    sRed2[grp * 32 + h] = ssum;
    __syncthreads();
    float S = 0.f;
    #pragma unroll
    for (int gg = 0; gg < 8; gg++) S += sRed2[gg * 32 + h];
    if (grp == 0) sInv[h] = 1.f / S;
    __syncthreads();

    // pack normalized weights: warp pw handles heads pw*4..pw*4+3
    int pw = tid >> 5, ln = tid & 31;
    int hh = pw * 4 + (ln >> 3), q = ln & 7;
    float invh = sInv[hh];
    size_t rowbase = (((size_t)b * 32 + hh) * 256 + l) * 128;
    #pragma unroll
    for (int i = 0; i < 4; i++) {
        int wd0 = i * 32 + q * 4;
        uint4 out;
        uint32_t* po = (uint32_t*)&out;
        #pragma unroll
        for (int ee = 0; ee < 4; ee++) {
            int m0 = 2 * (wd0 + ee);
            po[ee] = packbf(sH[m0 * 36 + hh] * invh, sH[(m0 + 1) * 36 + hh] * invh);
        }
        *(uint4*)&g_Wt[rowbase + wd0] = out;
    }
}

// ---- eb2: per-(b,h) GEMM  V_att[l, k] = W(256l x 256m) @ V_h(256m x 16k) -----
constexpr int EB2_SMEM_BYTES = (256 * 36 + 128 * 17) * 4;   // 45568

__global__ void __launch_bounds__(256) eb2_kernel()
{
    extern __shared__ uint32_t es2[];
    uint32_t* sA  = es2;            // 256 rows x 36 (32 kpair words + pad)
    uint32_t* sVb = es2 + 9216;     // 128 mpairs x 17 (16 n words + pad)

    int blk = blockIdx.x;
    int h = blk & 31, b = blk >> 5;
    int tid = threadIdx.x;
    int w = tid >> 5, g = (tid & 31) >> 2, qt = tid & 3;

    // build sVb[mp*17 + n] = (V[2mp][n] lo, V[2mp+1][n] hi) for this head
    const uint32_t* vb = (const uint32_t*)g_vb + (size_t)(b * 256) * 256 + h;
    #pragma unroll
    for (int it = 0; it < 8; it++) {
        int widx = tid + it * 256;      // 0..2047
        int mp = widx >> 4, n = widx & 15;
        int dp = n >> 1, s = n & 1;
        uint32_t w0 = vb[(size_t)(2 * mp)     * 256 + dp * 32];
        uint32_t w1 = vb[(size_t)(2 * mp + 1) * 256 + dp * 32];
        uint32_t lo = s ? (w0 >> 16) : (w0 & 0xffffu);
        uint32_t hi = s ? (w1 & 0xffff0000u) : (w1 << 16);
        sVb[mp * 17 + n] = lo | hi;
    }

    size_t Abase = ((size_t)b * 32 + h) * 256 * 128;
    float acc[2][2][4] = {};
    for (int c = 0; c < 4; c++) {
        __syncthreads();
        #pragma unroll
        for (int it = 0; it < 8; it++) {
            int v = tid + it * 256;     // 0..2047 uint4
            int row = v >> 3, wq = v & 7;
            uint4 av = *(const uint4*)&g_Wt[Abase + (size_t)row * 128 + c * 32 + wq * 4];
            *(uint4*)&sA[row * 36 + wq * 4] = av;
        }
        __syncthreads();
        #pragma unroll
        for (int s = 0; s < 4; s++) {
            int kp0 = 8 * s + qt;
            #pragma unroll
            for (int tm = 0; tm < 2; tm++) {
                const uint32_t* Ar = sA + (w * 32 + tm * 16) * 36;
                uint32_t a0 = Ar[(g)     * 36 + kp0];
                uint32_t a1 = Ar[(g + 8) * 36 + kp0];
                uint32_t a2 = Ar[(g)     * 36 + kp0 + 4];
                uint32_t a3 = Ar[(g + 8) * 36 + kp0 + 4];
                #pragma unroll
                for (int j = 0; j < 2; j++) {
                    uint32_t b0 = sVb[(32 * c + kp0)     * 17 + j * 8 + g];
                    uint32_t b1 = sVb[(32 * c + kp0 + 4) * 17 + j * 8 + g];
                    mma16(acc[tm][j], a0, a1, a2, a3, b0, b1);
                }
            }
        }
    }
    // epilogue: V_att[l, n*32 + h]
    float* Vout = g_vatt + (size_t)(b * 256) * 512 + h;
    #pragma unroll
    for (int tm = 0; tm < 2; tm++)
        #pragma unroll
        for (int j = 0; j < 2; j++) {
            int n = j * 8 + 2 * qt;
            #pragma unroll
            for (int hf = 0; hf < 2; hf++) {
                int l = w * 32 + tm * 16 + g + hf * 8;
                Vout[(size_t)l * 512 + n * 32]       = acc[tm][j][hf * 2 + 0];
                Vout[(size_t)l * 512 + (n + 1) * 32] = acc[tm][j][hf * 2 + 1];
            }
        }
}

// ---------------- launch ----------------
extern "C" void kernel_launch(void* const* d_in, const int* in_sizes, int n_in,
                              void* d_out, int out_size)
{
    const float* h         = (const float*)d_in[0];
    const float* e         = (const float*)d_in[1];
    const float* mask      = (const float*)d_in[2];
    const float* ln_h_g    = (const float*)d_in[3];
    const float* ln_h_b    = (const float*)d_in[4];
    const float* ln_e_g    = (const float*)d_in[5];
    const float* ln_e_b    = (const float*)d_in[6];
    const float* ffn_ln_h_g= (const float*)d_in[7];
    const float* ffn_ln_h_b= (const float*)d_in[8];
    const float* ffn_ln_e_g= (const float*)d_in[9];
    const float* ffn_ln_e_b= (const float*)d_in[10];
    const float* W_qkv     = (const float*)d_in[11];
    const float* b_qkv     = (const float*)d_in[12];
    const float* W_E       = (const float*)d_in[13];
    const float* b_E       = (const float*)d_in[14];
    const float* W_G       = (const float*)d_in[15];
    const float* b_G       = (const float*)d_in[16];
    const float* W_Oh      = (const float*)d_in[17];
    const float* b_Oh      = (const float*)d_in[18];
    const float* W_h1      = (const float*)d_in[19];
    const float* b_h1      = (const float*)d_in[20];
    const float* W_h2      = (const float*)d_in[21];
    const float* b_h2      = (const float*)d_in[22];
    const float* W_Oe      = (const float*)d_in[23];
    const float* b_Oe      = (const float*)d_in[24];
    const float* W_e1      = (const float*)d_in[25];
    const float* b_e1      = (const float*)d_in[26];
    const float* W_e2      = (const float*)d_in[27];
    const float* b_e2      = (const float*)d_in[28];

    float* h_out = (float*)d_out;
    float* e_out = (float*)d_out + (size_t)ROWS * DNn;

    float *p_hln, *p_qkv, *p_vatt, *p_h2, *p_hff, *p_t;
    cudaGetSymbolAddress((void**)&p_hln,  g_hln);
    cudaGetSymbolAddress((void**)&p_qkv,  g_qkv);
    cudaGetSymbolAddress((void**)&p_vatt, g_vatt);
    cudaGetSymbolAddress((void**)&p_h2,   g_h2);
    cudaGetSymbolAddress((void**)&p_hff,  g_hff);
    cudaGetSymbolAddress((void**)&p_t,    g_t);

    cudaFuncSetAttribute(ea_kernel, cudaFuncAttributeMaxDynamicSharedMemorySize,
                         EA_SMEM_BYTES);
    cudaFuncSetAttribute(qk_kernel, cudaFuncAttributeMaxDynamicSharedMemorySize,
                         QK_SMEM_BYTES);
    cudaFuncSetAttribute(eb2_kernel, cudaFuncAttributeMaxDynamicSharedMemorySize,
                         EB2_SMEM_BYTES);
    cudaFuncSetAttribute(tgemm_tf<1>, cudaFuncAttributeMaxDynamicSharedMemorySize,
                         TG_SMEM_BYTES);
    cudaFuncSetAttribute(tgemm_tf<2>, cudaFuncAttributeMaxDynamicSharedMemorySize,
                         TG_SMEM_BYTES);
    cudaFuncSetAttribute(tgemm_tf<3>, cudaFuncAttributeMaxDynamicSharedMemorySize,
                         TG_SMEM_BYTES);

    // 0) pack edge weights (bf16 fragments)
    pack_weights<<<88, 256>>>(W_E, W_G, W_Oe, W_e1, W_e2);
    // 1) h_ln
    ln512_kernel<<<ROWS, 128>>>(h, ln_h_g, ln_h_b, p_hln);
    // 2) QKV (tf32); Q -> g_qkv fp32, K/V -> g_kb/g_vb bf16 (fused pack)
    tgemm_tf<3><<<dim3(1536/64, ROWS/128), 256, TG_SMEM_BYTES>>>(p_hln, W_qkv, p_qkv,
                                                  b_qkv, nullptr, ROWS, 1536, 512);
    // 2.6) QK precompute: A_hat
    qk_kernel<<<Bn * 4 * 8, 256, QK_SMEM_BYTES>>>();
    // 3) edge pipeline (writes e_out, g_Hb(+mask), g_gateb)
    ea_kernel<<<ROWS * 4, 256, EA_SMEM_BYTES>>>(e, mask, ln_e_g, ln_e_b,
        ffn_ln_e_g, ffn_ln_e_b, b_E, b_G, b_Oe, b_e1, b_e2, e_out);
    // 4a) softmax -> normalized bf16 weights (g_Wt)
    eb1_kernel<<<ROWS, 256>>>();
    // 4b) per-head GEMM: V_att = W @ V_h  (V read once per head)
    eb2_kernel<<<Bn * 32, 256, EB2_SMEM_BYTES>>>();
    // 5) h2 = V_att @ W_Oh + b + h
    tgemm_tf<1><<<dim3(512/64, ROWS/128), 256, TG_SMEM_BYTES>>>(p_vatt, W_Oh, p_h2,
                                                 b_Oh, h, ROWS, 512, 512);
    // 6) h_ff = LN(h2)
    ln512_kernel<<<ROWS, 128>>>(p_h2, ffn_ln_h_g, ffn_ln_h_b, p_hff);
    // 7) t = elu(h_ff @ W_h1 + b)
    tgemm_tf<2><<<dim3(1024/64, ROWS/128), 256, TG_SMEM_BYTES>>>(p_hff, W_h1, p_t,
                                                  b_h1, nullptr, ROWS, 1024, 512);
    // 8) h_out = t @ W_h2 + b + h2
    tgemm_tf<1><<<dim3(512/64, ROWS/128), 256, TG_SMEM_BYTES>>>(p_t, W_h2, h_out,
                                                 b_h2, p_h2, ROWS, 512, 1024);
}